// round 1
// baseline (speedup 1.0000x reference)
#include <cuda_runtime.h>
#include <math.h>

#define BATCH 2048
#define NMEAS 128
#define MDIM  256
#define LNUM  10

// ---------------- scratch (device globals; no allocation allowed) ----------
__device__ float g_AAr[MDIM*MDIM], g_AAi[MDIM*MDIM];
__device__ float g_Atr[MDIM*NMEAS], g_Ati[MDIM*NMEAS];   // A transposed: [m][n]
__device__ float g_D[MDIM];
__device__ float g_AYr[BATCH*MDIM], g_AYi[BATCH*MDIM];
__device__ float g_F1[32*MDIM*BATCH];                    // conv1 output (relu), [oc][h=m][w=b]
__device__ float g_fm[64*BATCH];                         // mean over h, [oc][b]
__device__ float g_c[BATCH*9], g_d[BATCH*9], g_T[BATCH*10];
__device__ float g_Ur[2][BATCH*MDIM], g_Ui[2][BATCH*MDIM];
__device__ float g_Lam[BATCH*MDIM], g_Sig[BATCH*MDIM];
__device__ float g_eps[BATCH], g_eps2[BATCH];
__device__ unsigned int g_max;

// ---------------- K0: AA = A^H A, D = diag, At = A^T, zero g_max ----------
__global__ void k_prep(const float* __restrict__ Ar, const float* __restrict__ Ai) {
    int i = blockIdx.x, j = threadIdx.x;
    __shared__ float cr[NMEAS], ci[NMEAS];
    if (j < NMEAS) { cr[j] = Ar[j*MDIM + i]; ci[j] = Ai[j*MDIM + i]; }
    __syncthreads();
    float sr = 0.f, si = 0.f;
    for (int n = 0; n < NMEAS; n++) {
        float arj = Ar[n*MDIM + j], aij = Ai[n*MDIM + j];
        sr += cr[n]*arj + ci[n]*aij;   // conj(A[:,i]) . A[:,j]
        si += cr[n]*aij - ci[n]*arj;
    }
    g_AAr[i*MDIM + j] = sr;
    g_AAi[i*MDIM + j] = si;
    if (j == i) g_D[i] = sr;
    if (j < NMEAS) { g_Atr[i*NMEAS + j] = cr[j]; g_Ati[i*NMEAS + j] = ci[j]; }
    if (i == 0 && j == 0) g_max = 0u;
}

// ---------------- K1: AY = A^H Y, 8 batches per block ----------------------
__global__ void k_ay(const float* __restrict__ Yr, const float* __restrict__ Yi,
                     const float* __restrict__ Ar, const float* __restrict__ Ai) {
    int b0 = blockIdx.x * 8;
    __shared__ float sYr[8][NMEAS], sYi[8][NMEAS];
    for (int idx = threadIdx.x; idx < 8*NMEAS; idx += 256) {
        int bl = idx >> 7, n = idx & 127;
        sYr[bl][n] = Yr[(b0 + bl)*NMEAS + n];
        sYi[bl][n] = Yi[(b0 + bl)*NMEAS + n];
    }
    __syncthreads();
    int m = threadIdx.x;
    float ayr[8], ayi[8];
    #pragma unroll
    for (int q = 0; q < 8; q++) { ayr[q] = 0.f; ayi[q] = 0.f; }
    for (int n = 0; n < NMEAS; n++) {
        float ar = Ar[n*MDIM + m], ai = Ai[n*MDIM + m];
        #pragma unroll
        for (int q = 0; q < 8; q++) {
            float yr = sYr[q][n], yi = sYi[q][n];
            ayr[q] += ar*yr + ai*yi;
            ayi[q] += ar*yi - ai*yr;
        }
    }
    #pragma unroll
    for (int q = 0; q < 8; q++) {
        g_AYr[(b0 + q)*MDIM + m] = ayr[q];
        g_AYi[(b0 + q)*MDIM + m] = ayi[q];
    }
}

// ---------------- K2: conv1 (2->32 ch, 3x3 SAME) + relu -------------------
// image: x[ic][h=m][w=b], x[0]=AYr[b][m], x[1]=AYi[b][m]
__global__ void k_conv1(const float* __restrict__ w1, const float* __restrict__ b1) {
    int w0 = blockIdx.x * 32, h0 = blockIdx.y * 8;
    __shared__ float xs[2][10][34];
    __shared__ float ws[576];
    __shared__ float bs[32];
    int tid = threadIdx.x;
    for (int idx = tid; idx < 680; idx += 256) {
        int ic = idx / 340, r = idx % 340, hl = r / 34, wl = r % 34;
        int h = h0 - 1 + hl, w = w0 - 1 + wl;
        float v = 0.f;
        if (h >= 0 && h < MDIM && w >= 0 && w < BATCH)
            v = ic ? g_AYi[w*MDIM + h] : g_AYr[w*MDIM + h];
        xs[ic][hl][wl] = v;
    }
    for (int idx = tid; idx < 576; idx += 256) ws[idx] = w1[idx];
    if (tid < 32) bs[tid] = b1[tid];
    __syncthreads();
    int hl = tid / 32, wl = tid % 32;
    float xv[18];
    #pragma unroll
    for (int ic = 0; ic < 2; ic++)
        #pragma unroll
        for (int kh = 0; kh < 3; kh++)
            #pragma unroll
            for (int kw = 0; kw < 3; kw++)
                xv[ic*9 + kh*3 + kw] = xs[ic][hl + kh][wl + kw];
    int h = h0 + hl, w = w0 + wl;
    for (int oc = 0; oc < 32; oc++) {
        float a = bs[oc];
        #pragma unroll
        for (int t = 0; t < 18; t++) a += xv[t] * ws[oc*18 + t];
        g_F1[(oc*MDIM + h)*BATCH + w] = fmaxf(a, 0.f);
    }
}

// ---------------- K3: conv2 (32->64) + relu + mean over h ------------------
// block = 16-wide w-tile, full h sweep in 16 chunks. dyn smem: weights+data.
extern __shared__ float sm2[];
__global__ void k_conv2(const float* __restrict__ w2, const float* __restrict__ b2) {
    float* wsm = sm2;            // 64*32*9 = 18432
    float* dat = sm2 + 18432;    // 32*18*18 = 10368
    __shared__ float bs[64];
    int tid = threadIdx.x;
    int w0 = blockIdx.x * 16;
    for (int idx = tid; idx < 18432; idx += 256) wsm[idx] = w2[idx];
    if (tid < 64) bs[tid] = b2[tid];
    int wl = tid & 15, og = tid >> 4;
    int ocb = og * 4;
    float sum4[4] = {0.f, 0.f, 0.f, 0.f};
    for (int hc = 0; hc < 16; hc++) {
        int hb = hc * 16;
        __syncthreads();
        for (int idx = tid; idx < 10368; idx += 256) {
            int ic = idx / 324, r = idx % 324, hl = r / 18, wll = r % 18;
            int h = hb - 1 + hl, w = w0 - 1 + wll;
            dat[idx] = (h >= 0 && h < MDIM && w >= 0 && w < BATCH)
                       ? g_F1[(ic*MDIM + h)*BATCH + w] : 0.f;
        }
        __syncthreads();
        for (int hg = 0; hg < 16; hg += 8) {
            float acc[4][8];
            #pragma unroll
            for (int o = 0; o < 4; o++)
                #pragma unroll
                for (int hh = 0; hh < 8; hh++) acc[o][hh] = bs[ocb + o];
            for (int ic = 0; ic < 32; ic++) {
                const float* wrow = wsm + ocb*288 + ic*9;
                const float* db = dat + ic*324 + wl;
                #pragma unroll
                for (int t = 0; t < 9; t++) {
                    int kh = t / 3, kw = t % 3;
                    float w0v = wrow[t], w1v = wrow[288 + t];
                    float w2v = wrow[576 + t], w3v = wrow[864 + t];
                    const float* dp = db + (hg + kh)*18 + kw;
                    #pragma unroll
                    for (int hh = 0; hh < 8; hh++) {
                        float x = dp[hh*18];
                        acc[0][hh] += w0v * x;
                        acc[1][hh] += w1v * x;
                        acc[2][hh] += w2v * x;
                        acc[3][hh] += w3v * x;
                    }
                }
            }
            #pragma unroll
            for (int o = 0; o < 4; o++)
                #pragma unroll
                for (int hh = 0; hh < 8; hh++) sum4[o] += fmaxf(acc[o][hh], 0.f);
        }
    }
    #pragma unroll
    for (int o = 0; o < 4; o++)
        g_fm[(ocb + o)*BATCH + w0 + wl] = sum4[o] * (1.f / 256.f);
}

// ---------------- K4: conv1d heads -> c, d, T ------------------------------
__global__ void k_heads(const float* __restrict__ hcw, const float* __restrict__ hcb,
                        const float* __restrict__ hdw, const float* __restrict__ hdb,
                        const float* __restrict__ hTw, const float* __restrict__ hTb) {
    int b = blockIdx.x * 256 + threadIdx.x;
    int l = blockIdx.y;   // 0..27
    const float* W; float bias; int kind; int li;
    if (l < 9)       { li = l;      W = hcw + li*192; bias = hcb[li]; kind = 0; }
    else if (l < 18) { li = l - 9;  W = hdw + li*192; bias = hdb[li]; kind = 1; }
    else             { li = l - 18; W = hTw + li*192; bias = hTb[li]; kind = 2; }
    float a = bias;
    for (int ic = 0; ic < 64; ic++) {
        const float* f = g_fm + ic*BATCH;
        float x0 = (b > 0)         ? f[b - 1] : 0.f;
        float x1 = f[b];
        float x2 = (b < BATCH - 1) ? f[b + 1] : 0.f;
        a += W[ic*3 + 0]*x0 + W[ic*3 + 1]*x1 + W[ic*3 + 2]*x2;
    }
    float v = fabsf(a);
    if (kind == 0)      { v = fminf(fmaxf(v, 1e-6f), 100.f); g_c[b*9 + li] = v; }
    else if (kind == 1) { v = fmaxf(v, 1e-6f);               g_d[b*9 + li] = v; }
    else                { v = fminf(fmaxf(v, 1e-6f), 100.f); g_T[b*10 + li] = v; }
}

// ---------------- K5: init eps, Lam, U=0 -----------------------------------
__global__ void k_init(const float* __restrict__ a0, const float* __restrict__ b0) {
    int b = blockIdx.x, m = threadIdx.x;
    if (m == 0) g_eps[b] = a0[0] / b0[0];
    float lam = g_c[b*9] / g_d[b*9];
    g_Lam[b*MDIM + m] = lam;
    g_Ur[0][b*MDIM + m] = 0.f;
    g_Ui[0][b*MDIM + m] = 0.f;
}

// ---------------- K6: fused AA@U GEMM + U update ---------------------------
// tiles: 64 b x 64 i, k-chunk 16, thread does 4x4 complex outputs
__global__ void k_gemmU(int k, int src, int dst) {
    __shared__ float Usr[16*64], Usi[16*64], Asr[16*64], Asi[16*64];
    int tid = threadIdx.x;
    int b0 = blockIdx.x * 64, i0 = blockIdx.y * 64;
    int tx = tid & 15, ty = tid >> 4;
    float cr[4][4], ci4[4][4];
    #pragma unroll
    for (int u = 0; u < 4; u++)
        #pragma unroll
        for (int v = 0; v < 4; v++) { cr[u][v] = 0.f; ci4[u][v] = 0.f; }
    const float* Urp = g_Ur[src];
    const float* Uip = g_Ui[src];
    for (int jc = 0; jc < MDIM; jc += 16) {
        __syncthreads();
        for (int idx = tid; idx < 1024; idx += 256) {
            int jl = idx & 15, l = idx >> 4;
            Usr[jl*64 + l] = Urp[(b0 + l)*MDIM + jc + jl];
            Usi[jl*64 + l] = Uip[(b0 + l)*MDIM + jc + jl];
            Asr[jl*64 + l] = g_AAr[(i0 + l)*MDIM + jc + jl];
            Asi[jl*64 + l] = g_AAi[(i0 + l)*MDIM + jc + jl];
        }
        __syncthreads();
        for (int j = 0; j < 16; j++) {
            float ur[4], ui[4], ar[4], ai[4];
            #pragma unroll
            for (int u = 0; u < 4; u++) {
                ur[u] = Usr[j*64 + ty + 16*u];
                ui[u] = Usi[j*64 + ty + 16*u];
            }
            #pragma unroll
            for (int v = 0; v < 4; v++) {
                ar[v] = Asr[j*64 + tx + 16*v];
                ai[v] = Asi[j*64 + tx + 16*v];
            }
            #pragma unroll
            for (int u = 0; u < 4; u++)
                #pragma unroll
                for (int v = 0; v < 4; v++) {
                    cr[u][v]  += ar[v]*ur[u] - ai[v]*ui[u];
                    ci4[u][v] += ar[v]*ui[u] + ai[v]*ur[u];
                }
        }
    }
    #pragma unroll
    for (int u = 0; u < 4; u++) {
        int b = b0 + ty + 16*u;
        float Tk = g_T[b*10 + k], e = g_eps[b];
        #pragma unroll
        for (int v = 0; v < 4; v++) {
            int i = i0 + tx + 16*v;
            float lam = g_Lam[b*MDIM + i];
            float uor = Urp[b*MDIM + i], uoi = Uip[b*MDIM + i];
            float inv = e / (e*Tk + lam + 1e-6f);
            g_Ur[dst][b*MDIM + i] = inv * (Tk*uor - cr[u][v]  + g_AYr[b*MDIM + i]);
            g_Ui[dst][b*MDIM + i] = inv * (Tk*uoi - ci4[u][v] + g_AYi[b*MDIM + i]);
        }
    }
}

// ---------------- K7: Sigma + eps2 (uses OLD eps, OLD Lam) -----------------
__global__ void k_sig() {
    int b = blockIdx.x, m = threadIdx.x;
    float e = g_eps[b];
    float lam = g_Lam[b*MDIM + m];
    float Dm = g_D[m];
    float sig = 1.f / (e*Dm + lam + 1e-6f);
    g_Sig[b*MDIM + m] = sig;
    __shared__ float red[256];
    red[m] = Dm * sig;
    __syncthreads();
    for (int s = 128; s > 0; s >>= 1) {
        if (m < s) red[m] += red[m + s];
        __syncthreads();
    }
    if (m == 0) g_eps2[b] = red[0];
}

// ---------------- K8: residual r = Y - A U, eps1, eps update, Lam update ---
__global__ void k_post(int k, int dst,
                       const float* __restrict__ Yr, const float* __restrict__ Yi,
                       const float* __restrict__ a0p, const float* __restrict__ b0p) {
    int b0 = blockIdx.x * 8;
    int tid = threadIdx.x;
    __shared__ float sUr[8][MDIM], sUi[8][MDIM];
    __shared__ float sq[8][128];
    const float* Urp = g_Ur[dst];
    const float* Uip = g_Ui[dst];
    for (int idx = tid; idx < 8*MDIM; idx += 256) {
        int bl = idx >> 8, m = idx & 255;
        sUr[bl][m] = Urp[(b0 + bl)*MDIM + m];
        sUi[bl][m] = Uip[(b0 + bl)*MDIM + m];
    }
    __syncthreads();
    int n = tid & 127, g = tid >> 7;
    float rr[4], ri[4];
    #pragma unroll
    for (int q = 0; q < 4; q++) {
        int bb = g*4 + q;
        rr[q] = Yr[(b0 + bb)*NMEAS + n];
        ri[q] = Yi[(b0 + bb)*NMEAS + n];
    }
    for (int m = 0; m < MDIM; m++) {
        float ar = g_Atr[m*NMEAS + n], ai = g_Ati[m*NMEAS + n];
        #pragma unroll
        for (int q = 0; q < 4; q++) {
            int bb = g*4 + q;
            float ur = sUr[bb][m], ui = sUi[bb][m];
            rr[q] -= ar*ur - ai*ui;
            ri[q] -= ar*ui + ai*ur;
        }
    }
    #pragma unroll
    for (int q = 0; q < 4; q++)
        sq[g*4 + q][n] = rr[q]*rr[q] + ri[q]*ri[q];
    __syncthreads();
    int wq = tid >> 5, lane = tid & 31;
    float s = sq[wq][lane] + sq[wq][lane + 32] + sq[wq][lane + 64] + sq[wq][lane + 96];
    #pragma unroll
    for (int o = 16; o > 0; o >>= 1) s += __shfl_down_sync(0xffffffffu, s, o);
    if (lane == 0) {
        float a = a0p[0] + (float)NMEAS;
        g_eps[b0 + wq] = a / (b0p[0] + s + g_eps2[b0 + wq] + 1e-6f);
    }
    for (int idx = tid; idx < 8*MDIM; idx += 256) {
        int bl = idx >> 8, m = idx & 255;
        int b = b0 + bl;
        float ur = sUr[bl][m], ui = sUi[bl][m];
        float ck = g_c[b*9 + k], dk = g_d[b*9 + k];
        g_Lam[b*MDIM + m] = (ck + 1.f) / (dk + ur*ur + ui*ui + g_Sig[b*MDIM + m] + 1e-6f);
    }
}

// ---------------- K9: |U| -> out, global max -------------------------------
__global__ void k_abs(int fin, float* __restrict__ out) {
    int idx = blockIdx.x * 256 + threadIdx.x;
    float ur = g_Ur[fin][idx], ui = g_Ui[fin][idx];
    float v = sqrtf(ur*ur + ui*ui);
    out[idx] = v;
    __shared__ float red[256];
    red[threadIdx.x] = v;
    __syncthreads();
    for (int s = 128; s > 0; s >>= 1) {
        if (threadIdx.x < s) red[threadIdx.x] = fmaxf(red[threadIdx.x], red[threadIdx.x + s]);
        __syncthreads();
    }
    if (threadIdx.x == 0) atomicMax(&g_max, __float_as_uint(red[0]));
}

// ---------------- K10: scale + diagnostic tails ----------------------------
__global__ void k_final(float* __restrict__ out) {
    int bid = blockIdx.x;
    if (bid < BATCH) {
        int idx = bid * 256 + threadIdx.x;
        float mx = __uint_as_float(g_max);
        out[idx] = out[idx] / (mx + 1e-8f);
    } else {
        int t = threadIdx.x;
        int base = BATCH * MDIM;
        if (t < 9)       out[base + t] = g_c[(BATCH - 1)*9 + t];
        else if (t < 18) out[base + t] = g_d[(BATCH - 1)*9 + (t - 9)];
        else if (t < 28) out[base + t] = g_T[(BATCH - 1)*10 + (t - 18)];
    }
}

// ---------------- launch ---------------------------------------------------
extern "C" void kernel_launch(void* const* d_in, const int* in_sizes, int n_in,
                              void* d_out, int out_size) {
    const float* Yr  = (const float*)d_in[0];
    const float* Yi  = (const float*)d_in[1];
    const float* Ar  = (const float*)d_in[2];
    const float* Ai  = (const float*)d_in[3];
    const float* c1w = (const float*)d_in[4];
    const float* c1b = (const float*)d_in[5];
    const float* c2w = (const float*)d_in[6];
    const float* c2b = (const float*)d_in[7];
    const float* hcw = (const float*)d_in[8];
    const float* hcb = (const float*)d_in[9];
    const float* hdw = (const float*)d_in[10];
    const float* hdb = (const float*)d_in[11];
    const float* hTw = (const float*)d_in[12];
    const float* hTb = (const float*)d_in[13];
    const float* a0  = (const float*)d_in[14];
    const float* b0  = (const float*)d_in[15];
    float* out = (float*)d_out;

    cudaFuncSetAttribute(k_conv2, cudaFuncAttributeMaxDynamicSharedMemorySize, 115200);

    k_prep<<<256, 256>>>(Ar, Ai);
    k_ay<<<256, 256>>>(Yr, Yi, Ar, Ai);
    k_conv1<<<dim3(64, 32), 256>>>(c1w, c1b);
    k_conv2<<<128, 256, 115200>>>(c2w, c2b);
    k_heads<<<dim3(8, 28), 256>>>(hcw, hcb, hdw, hdb, hTw, hTb);
    k_init<<<BATCH, 256>>>(a0, b0);

    int src = 0;
    for (int k = 0; k < LNUM - 1; k++) {
        int dst = 1 - src;
        k_gemmU<<<dim3(32, 4), 256>>>(k, src, dst);
        k_sig<<<BATCH, 256>>>();
        k_post<<<256, 256>>>(k, dst, Yr, Yi, a0, b0);
        src = dst;
    }
    int dst = 1 - src;
    k_gemmU<<<dim3(32, 4), 256>>>(LNUM - 1, src, dst);
    k_abs<<<2048, 256>>>(dst, out);
    k_final<<<2049, 256>>>(out);
}

// round 2
// speedup vs baseline: 1.2052x; 1.2052x over previous
#include <cuda_runtime.h>
#include <math.h>

#define BATCH 2048
#define NMEAS 128
#define MDIM  256
#define LNUM  10

typedef unsigned long long ull;

__device__ __forceinline__ ull pk2(float x, float y) {
    ull r; asm("mov.b64 %0, {%1, %2};" : "=l"(r) : "f"(x), "f"(y)); return r;
}
__device__ __forceinline__ float2 upk2(ull v) {
    float2 t; asm("mov.b64 {%0, %1}, %2;" : "=f"(t.x), "=f"(t.y) : "l"(v)); return t;
}
__device__ __forceinline__ void fma2(ull& d, ull a, ull b) {
    asm("fma.rn.f32x2 %0, %1, %2, %3;" : "=l"(d) : "l"(a), "l"(b), "l"(d));
}

// ---------------- scratch ----------------
__device__ float g_AAr[MDIM*MDIM], g_AAi[MDIM*MDIM];
__device__ float2 g_At2[MDIM*NMEAS];                     // interleaved (Ar,Ai), [m][n]
__device__ float g_D[MDIM];
__device__ float g_AYr[BATCH*MDIM], g_AYi[BATCH*MDIM];
__device__ float g_F1[32*MDIM*BATCH];                    // conv1 out, [oc][h=m][w=b]
__device__ float g_fmp[2*64*BATCH];                      // partial means, [half][oc][b]
__device__ float g_c[BATCH*9], g_d[BATCH*9], g_T[BATCH*10];
__device__ float g_Ur[2][BATCH*MDIM], g_Ui[2][BATCH*MDIM];
__device__ float g_Lam[BATCH*MDIM];
__device__ float g_eps[BATCH];
__device__ unsigned int g_max;

// ---------------- K0: AA = A^H A, D, At2, init g_max ----------
__global__ void k_prep(const float* __restrict__ Ar, const float* __restrict__ Ai) {
    int i = blockIdx.x, j = threadIdx.x;
    __shared__ float cr[NMEAS], ci[NMEAS];
    if (j < NMEAS) { cr[j] = Ar[j*MDIM + i]; ci[j] = Ai[j*MDIM + i]; }
    __syncthreads();
    float sr = 0.f, si = 0.f;
    for (int n = 0; n < NMEAS; n++) {
        float arj = Ar[n*MDIM + j], aij = Ai[n*MDIM + j];
        sr += cr[n]*arj + ci[n]*aij;
        si += cr[n]*aij - ci[n]*arj;
    }
    g_AAr[i*MDIM + j] = sr;
    g_AAi[i*MDIM + j] = si;
    if (j == i) g_D[i] = sr;
    if (j < NMEAS) g_At2[i*NMEAS + j] = make_float2(cr[j], ci[j]);
    if (i == 0 && j == 0) g_max = 0u;
}

// ---------------- K1: AY = A^H Y ----------------------
__global__ void k_ay(const float* __restrict__ Yr, const float* __restrict__ Yi,
                     const float* __restrict__ Ar, const float* __restrict__ Ai) {
    int b0 = blockIdx.x * 8;
    __shared__ float sYr[8][NMEAS], sYi[8][NMEAS];
    for (int idx = threadIdx.x; idx < 8*NMEAS; idx += 256) {
        int bl = idx >> 7, n = idx & 127;
        sYr[bl][n] = Yr[(b0 + bl)*NMEAS + n];
        sYi[bl][n] = Yi[(b0 + bl)*NMEAS + n];
    }
    __syncthreads();
    int m = threadIdx.x;
    float ayr[8], ayi[8];
    #pragma unroll
    for (int q = 0; q < 8; q++) { ayr[q] = 0.f; ayi[q] = 0.f; }
    for (int n = 0; n < NMEAS; n++) {
        float ar = Ar[n*MDIM + m], ai = Ai[n*MDIM + m];
        #pragma unroll
        for (int q = 0; q < 8; q++) {
            float yr = sYr[q][n], yi = sYi[q][n];
            ayr[q] += ar*yr + ai*yi;
            ayi[q] += ar*yi - ai*yr;
        }
    }
    #pragma unroll
    for (int q = 0; q < 8; q++) {
        g_AYr[(b0 + q)*MDIM + m] = ayr[q];
        g_AYi[(b0 + q)*MDIM + m] = ayi[q];
    }
}

// ---------------- K2: conv1 (2->32, 3x3) + relu -------------------
__global__ void k_conv1(const float* __restrict__ w1, const float* __restrict__ b1) {
    int w0 = blockIdx.x * 32, h0 = blockIdx.y * 8;
    __shared__ float xs[2][10][34];
    __shared__ float ws[576];
    __shared__ float bs[32];
    int tid = threadIdx.x;
    for (int idx = tid; idx < 680; idx += 256) {
        int ic = idx / 340, r = idx % 340, hl = r / 34, wl = r % 34;
        int h = h0 - 1 + hl, w = w0 - 1 + wl;
        float v = 0.f;
        if (h >= 0 && h < MDIM && w >= 0 && w < BATCH)
            v = ic ? g_AYi[w*MDIM + h] : g_AYr[w*MDIM + h];
        xs[ic][hl][wl] = v;
    }
    for (int idx = tid; idx < 576; idx += 256) ws[idx] = w1[idx];
    if (tid < 32) bs[tid] = b1[tid];
    __syncthreads();
    int hl = tid / 32, wl = tid % 32;
    float xv[18];
    #pragma unroll
    for (int ic = 0; ic < 2; ic++)
        #pragma unroll
        for (int kh = 0; kh < 3; kh++)
            #pragma unroll
            for (int kw = 0; kw < 3; kw++)
                xv[ic*9 + kh*3 + kw] = xs[ic][hl + kh][wl + kw];
    int h = h0 + hl, w = w0 + wl;
    for (int oc = 0; oc < 32; oc++) {
        float a = bs[oc];
        #pragma unroll
        for (int t = 0; t < 18; t++) a += xv[t] * ws[oc*18 + t];
        g_F1[(oc*MDIM + h)*BATCH + w] = fmaxf(a, 0.f);
    }
}

// ---------------- K3: conv2 (32->64) + relu + partial mean, f32x2 ----------
// grid (128 w-tiles, 2 h-halves). data smem layout [ic][w 18][h 18] h-contig.
extern __shared__ float sm2[];
__global__ __launch_bounds__(256) void k_conv2(const float* __restrict__ w2,
                                               const float* __restrict__ b2) {
    float* wsm = sm2;            // 18432
    float* dat = sm2 + 18432;    // 32*18*18 = 10368
    __shared__ float bs[64];
    int tid = threadIdx.x;
    int w0 = blockIdx.x * 16;
    int by = blockIdx.y;         // 0 or 1: h half
    for (int idx = tid; idx < 18432; idx += 256) wsm[idx] = w2[idx];
    if (tid < 64) bs[tid] = b2[tid];
    int wl = tid & 15, og = tid >> 4;
    int ocb = og * 4;
    float sum4[4] = {0.f, 0.f, 0.f, 0.f};
    for (int hc = 0; hc < 8; hc++) {
        int hb = by*128 + hc*16;
        __syncthreads();
        // fill dat: global w contiguous reads, transposed smem write
        for (int idx = tid; idx < 10368; idx += 256) {
            int ic = idx / 324, r = idx % 324, hl = r / 18, wll = r % 18;
            int h = hb - 1 + hl, w = w0 - 1 + wll;
            float v = (h >= 0 && h < MDIM && w >= 0 && w < BATCH)
                      ? g_F1[(ic*MDIM + h)*BATCH + w] : 0.f;
            dat[(ic*18 + wll)*18 + hl] = v;
        }
        __syncthreads();
        ull acc[4][8];
        #pragma unroll
        for (int o = 0; o < 4; o++) {
            ull bias2 = pk2(bs[ocb + o], bs[ocb + o]);
            #pragma unroll
            for (int p = 0; p < 8; p++) acc[o][p] = bias2;
        }
        for (int ic = 0; ic < 32; ic++) {
            const float* dcol = dat + ic*324;
            #pragma unroll
            for (int kw = 0; kw < 3; kw++) {
                const float* dp = dcol + (wl + kw)*18;
                float2 xe[9];
                #pragma unroll
                for (int t = 0; t < 9; t++) xe[t] = *(const float2*)(dp + 2*t);
                #pragma unroll
                for (int kh = 0; kh < 3; kh++) {
                    ull wp[4];
                    #pragma unroll
                    for (int o = 0; o < 4; o++) {
                        float wv = wsm[(ocb + o)*288 + ic*9 + kh*3 + kw];
                        wp[o] = pk2(wv, wv);
                    }
                    #pragma unroll
                    for (int p = 0; p < 8; p++) {
                        ull xv;
                        if (kh == 0)      xv = pk2(xe[p].x, xe[p].y);
                        else if (kh == 1) xv = pk2(xe[p].y, xe[p+1].x);
                        else              xv = pk2(xe[p+1].x, xe[p+1].y);
                        fma2(acc[0][p], wp[0], xv);
                        fma2(acc[1][p], wp[1], xv);
                        fma2(acc[2][p], wp[2], xv);
                        fma2(acc[3][p], wp[3], xv);
                    }
                }
            }
        }
        #pragma unroll
        for (int o = 0; o < 4; o++)
            #pragma unroll
            for (int p = 0; p < 8; p++) {
                float2 v = upk2(acc[o][p]);
                sum4[o] += fmaxf(v.x, 0.f) + fmaxf(v.y, 0.f);
            }
    }
    #pragma unroll
    for (int o = 0; o < 4; o++)
        g_fmp[(by*64 + ocb + o)*BATCH + w0 + wl] = sum4[o] * (1.f / 256.f);
}

// ---------------- K4: conv1d heads -> c, d, T ------------------------------
__global__ void k_heads(const float* __restrict__ hcw, const float* __restrict__ hcb,
                        const float* __restrict__ hdw, const float* __restrict__ hdb,
                        const float* __restrict__ hTw, const float* __restrict__ hTb) {
    int b = blockIdx.x * 256 + threadIdx.x;
    int l = blockIdx.y;
    const float* W; float bias; int kind; int li;
    if (l < 9)       { li = l;      W = hcw + li*192; bias = hcb[li]; kind = 0; }
    else if (l < 18) { li = l - 9;  W = hdw + li*192; bias = hdb[li]; kind = 1; }
    else             { li = l - 18; W = hTw + li*192; bias = hTb[li]; kind = 2; }
    float a = bias;
    for (int ic = 0; ic < 64; ic++) {
        const float* f0 = g_fmp + ic*BATCH;
        const float* f1 = g_fmp + (64 + ic)*BATCH;
        float x0 = (b > 0)         ? f0[b - 1] + f1[b - 1] : 0.f;
        float x1 = f0[b] + f1[b];
        float x2 = (b < BATCH - 1) ? f0[b + 1] + f1[b + 1] : 0.f;
        a += W[ic*3 + 0]*x0 + W[ic*3 + 1]*x1 + W[ic*3 + 2]*x2;
    }
    float v = fabsf(a);
    if (kind == 0)      { v = fminf(fmaxf(v, 1e-6f), 100.f); g_c[b*9 + li] = v; }
    else if (kind == 1) { v = fmaxf(v, 1e-6f);               g_d[b*9 + li] = v; }
    else                { v = fminf(fmaxf(v, 1e-6f), 100.f); g_T[b*10 + li] = v; }
}

// ---------------- K5: init ----------------------------------------
__global__ void k_init(const float* __restrict__ a0, const float* __restrict__ b0) {
    int b = blockIdx.x, m = threadIdx.x;
    if (m == 0) g_eps[b] = a0[0] / b0[0];
    float lam = g_c[b*9] / g_d[b*9];
    g_Lam[b*MDIM + m] = lam;
    g_Ur[0][b*MDIM + m] = 0.f;
    g_Ui[0][b*MDIM + m] = 0.f;
}

// ---------------- K6: fused AA@U GEMM + U update (f32x2) --------------------
// tile 64b x 64i, 128 threads (tx 0..7 over i, ty 0..15 over b), 4b x 8i/thread
// smem pitch 66 to avoid STS conflicts. acc packed (re,im).
__global__ __launch_bounds__(128) void k_gemmU(int k, int src, int dst) {
    __shared__ float sU[16*66*2];   // [j][b][ri], pitch 66
    __shared__ float sA[16*66*2];   // [j][i][ri], pitch 66
    int tid = threadIdx.x;
    int b0 = blockIdx.x * 64, i0 = blockIdx.y * 64;
    int tx = tid & 7, ty = tid >> 3;
    ull acc[4][8];
    #pragma unroll
    for (int u = 0; u < 4; u++)
        #pragma unroll
        for (int v = 0; v < 8; v++) acc[u][v] = 0ull;
    const float* Urp = g_Ur[src];
    const float* Uip = g_Ui[src];
    for (int jc = 0; jc < MDIM; jc += 16) {
        __syncthreads();
        for (int idx = tid; idx < 1024; idx += 128) {
            int l = idx >> 4, jl = idx & 15;
            float ur = Urp[(b0 + l)*MDIM + jc + jl];
            float ui = Uip[(b0 + l)*MDIM + jc + jl];
            *(ull*)&sU[(jl*66 + l)*2] = pk2(ur, ui);
            float ar = g_AAr[(i0 + l)*MDIM + jc + jl];
            float ai = g_AAi[(i0 + l)*MDIM + jc + jl];
            *(ull*)&sA[(jl*66 + l)*2] = pk2(ar, ai);
        }
        __syncthreads();
        #pragma unroll 4
        for (int j = 0; j < 16; j++) {
            ull u2[4], usw[4];
            #pragma unroll
            for (int u = 0; u < 4; u++) {
                float2 t = *(const float2*)&sU[(j*66 + ty + 16*u)*2];
                u2[u]  = pk2(t.x, t.y);
                usw[u] = pk2(-t.y, t.x);
            }
            #pragma unroll
            for (int v = 0; v < 8; v++) {
                float2 a = *(const float2*)&sA[(j*66 + tx + 8*v)*2];
                ull arr = pk2(a.x, a.x);
                ull aii = pk2(a.y, a.y);
                #pragma unroll
                for (int u = 0; u < 4; u++) {
                    fma2(acc[u][v], arr, u2[u]);
                    fma2(acc[u][v], aii, usw[u]);
                }
            }
        }
    }
    #pragma unroll
    for (int u = 0; u < 4; u++) {
        int b = b0 + ty + 16*u;
        float Tk = g_T[b*10 + k], e = g_eps[b];
        #pragma unroll
        for (int v = 0; v < 8; v++) {
            int i = i0 + tx + 8*v;
            float lam = g_Lam[b*MDIM + i];
            float uor = Urp[b*MDIM + i], uoi = Uip[b*MDIM + i];
            float inv = e / (e*Tk + lam + 1e-6f);
            float2 cc = upk2(acc[u][v]);
            g_Ur[dst][b*MDIM + i] = inv * (Tk*uor - cc.x + g_AYr[b*MDIM + i]);
            g_Ui[dst][b*MDIM + i] = inv * (Tk*uoi - cc.y + g_AYi[b*MDIM + i]);
        }
    }
}

// ---------------- K8: residual + eps1 + Sigma/eps2 + eps + Lam (fused) -----
__global__ __launch_bounds__(256) void k_post(int k, int dst,
                       const float* __restrict__ Yr, const float* __restrict__ Yi,
                       const float* __restrict__ a0p, const float* __restrict__ b0p) {
    int b0 = blockIdx.x * 8;
    int tid = threadIdx.x;
    __shared__ float2 sU2[8][256];
    __shared__ float sq[8][128];
    __shared__ float seps1[8];
    __shared__ float se[8];
    __shared__ float seps2s[8][8];
    const float* Urp = g_Ur[dst];
    const float* Uip = g_Ui[dst];
    if (tid < 8) se[tid] = g_eps[b0 + tid];   // OLD eps
    for (int idx = tid; idx < 8*MDIM; idx += 256) {
        int bl = idx >> 8, m = idx & 255;
        sU2[bl][m] = make_float2(Urp[(b0 + bl)*MDIM + m], Uip[(b0 + bl)*MDIM + m]);
    }
    __syncthreads();
    int n = tid & 127, g = tid >> 7;
    ull m2[4] = {0ull, 0ull, 0ull, 0ull};     // packed (re,im) of (A U)[n]
    #pragma unroll 2
    for (int m = 0; m < MDIM; m++) {
        float2 a2 = g_At2[m*NMEAS + n];
        ull arr = pk2(a2.x, a2.x);
        ull aii = pk2(a2.y, a2.y);
        #pragma unroll
        for (int q = 0; q < 4; q++) {
            float2 uv = sU2[g*4 + q][m];
            ull u2 = pk2(uv.x, uv.y);
            ull us = pk2(-uv.y, uv.x);
            fma2(m2[q], arr, u2);
            fma2(m2[q], aii, us);
        }
    }
    #pragma unroll
    for (int q = 0; q < 4; q++) {
        int bb = g*4 + q;
        float2 au = upk2(m2[q]);
        float rr = Yr[(b0 + bb)*NMEAS + n] - au.x;
        float ri = Yi[(b0 + bb)*NMEAS + n] - au.y;
        sq[bb][n] = rr*rr + ri*ri;
    }
    __syncthreads();
    {   // eps1: each warp reduces one batch
        int wq = tid >> 5, lane = tid & 31;
        float s = sq[wq][lane] + sq[wq][lane + 32] + sq[wq][lane + 64] + sq[wq][lane + 96];
        #pragma unroll
        for (int o = 16; o > 0; o >>= 1) s += __shfl_down_sync(0xffffffffu, s, o);
        if (lane == 0) seps1[wq] = s;
    }
    // Sigma (from OLD eps, OLD Lam), eps2 partials, Lam update. m = tid.
    float Dm = g_D[tid];
    float e2p[8];
    #pragma unroll
    for (int bl = 0; bl < 8; bl++) {
        int b = b0 + bl;
        float lam = g_Lam[b*MDIM + tid];
        float sig = 1.f / (se[bl]*Dm + lam + 1e-6f);
        float2 uv = sU2[bl][tid];
        float ck = g_c[b*9 + k], dk = g_d[b*9 + k];
        g_Lam[b*MDIM + tid] = (ck + 1.f) / (dk + uv.x*uv.x + uv.y*uv.y + sig + 1e-6f);
        e2p[bl] = Dm * sig;
    }
    int lane = tid & 31, wrp = tid >> 5;
    #pragma unroll
    for (int bl = 0; bl < 8; bl++) {
        float v = e2p[bl];
        #pragma unroll
        for (int o = 16; o > 0; o >>= 1) v += __shfl_down_sync(0xffffffffu, v, o);
        if (lane == 0) seps2s[wrp][bl] = v;
    }
    __syncthreads();
    if (tid < 8) {
        float s2 = 0.f;
        #pragma unroll
        for (int w = 0; w < 8; w++) s2 += seps2s[w][tid];
        float a = a0p[0] + (float)NMEAS;
        g_eps[b0 + tid] = a / (b0p[0] + seps1[tid] + s2 + 1e-6f);
    }
}

// ---------------- K9: |U| -> out, global max -------------------------------
__global__ void k_abs(int fin, float* __restrict__ out) {
    int idx = blockIdx.x * 256 + threadIdx.x;
    float ur = g_Ur[fin][idx], ui = g_Ui[fin][idx];
    float v = sqrtf(ur*ur + ui*ui);
    out[idx] = v;
    __shared__ float red[256];
    red[threadIdx.x] = v;
    __syncthreads();
    for (int s = 128; s > 0; s >>= 1) {
        if (threadIdx.x < s) red[threadIdx.x] = fmaxf(red[threadIdx.x], red[threadIdx.x + s]);
        __syncthreads();
    }
    if (threadIdx.x == 0) atomicMax(&g_max, __float_as_uint(red[0]));
}

// ---------------- K10: scale + diagnostic tails ----------------------------
__global__ void k_final(float* __restrict__ out) {
    int bid = blockIdx.x;
    if (bid < BATCH) {
        int idx = bid * 256 + threadIdx.x;
        float mx = __uint_as_float(g_max);
        out[idx] = out[idx] / (mx + 1e-8f);
    } else {
        int t = threadIdx.x;
        int base = BATCH * MDIM;
        if (t < 9)       out[base + t] = g_c[(BATCH - 1)*9 + t];
        else if (t < 18) out[base + t] = g_d[(BATCH - 1)*9 + (t - 9)];
        else if (t < 28) out[base + t] = g_T[(BATCH - 1)*10 + (t - 18)];
    }
}

// ---------------- launch ---------------------------------------------------
extern "C" void kernel_launch(void* const* d_in, const int* in_sizes, int n_in,
                              void* d_out, int out_size) {
    const float* Yr  = (const float*)d_in[0];
    const float* Yi  = (const float*)d_in[1];
    const float* Ar  = (const float*)d_in[2];
    const float* Ai  = (const float*)d_in[3];
    const float* c1w = (const float*)d_in[4];
    const float* c1b = (const float*)d_in[5];
    const float* c2w = (const float*)d_in[6];
    const float* c2b = (const float*)d_in[7];
    const float* hcw = (const float*)d_in[8];
    const float* hcb = (const float*)d_in[9];
    const float* hdw = (const float*)d_in[10];
    const float* hdb = (const float*)d_in[11];
    const float* hTw = (const float*)d_in[12];
    const float* hTb = (const float*)d_in[13];
    const float* a0  = (const float*)d_in[14];
    const float* b0  = (const float*)d_in[15];
    float* out = (float*)d_out;

    cudaFuncSetAttribute(k_conv2, cudaFuncAttributeMaxDynamicSharedMemorySize, 115200);

    k_prep<<<256, 256>>>(Ar, Ai);
    k_ay<<<256, 256>>>(Yr, Yi, Ar, Ai);
    k_conv1<<<dim3(64, 32), 256>>>(c1w, c1b);
    k_conv2<<<dim3(128, 2), 256, 115200>>>(c2w, c2b);
    k_heads<<<dim3(8, 28), 256>>>(hcw, hcb, hdw, hdb, hTw, hTb);
    k_init<<<BATCH, 256>>>(a0, b0);

    int src = 0;
    for (int k = 0; k < LNUM - 1; k++) {
        int dst = 1 - src;
        k_gemmU<<<dim3(32, 4), 128>>>(k, src, dst);
        k_post<<<256, 256>>>(k, dst, Yr, Yi, a0, b0);
        src = dst;
    }
    int dst = 1 - src;
    k_gemmU<<<dim3(32, 4), 128>>>(LNUM - 1, src, dst);
    k_abs<<<2048, 256>>>(dst, out);
    k_final<<<2049, 256>>>(out);
}

// round 3
// speedup vs baseline: 1.2300x; 1.0205x over previous
#include <cuda_runtime.h>
#include <math.h>

#define BATCH 2048
#define NMEAS 128
#define MDIM  256
#define LNUM  10

typedef unsigned long long ull;

__device__ __forceinline__ ull pk2(float x, float y) {
    ull r; asm("mov.b64 %0, {%1, %2};" : "=l"(r) : "f"(x), "f"(y)); return r;
}
__device__ __forceinline__ float2 upk2(ull v) {
    float2 t; asm("mov.b64 {%0, %1}, %2;" : "=f"(t.x), "=f"(t.y) : "l"(v)); return t;
}
__device__ __forceinline__ void fma2(ull& d, ull a, ull b) {
    asm("fma.rn.f32x2 %0, %1, %2, %3;" : "=l"(d) : "l"(a), "l"(b), "l"(d));
}

// ---------------- scratch ----------------
__device__ float g_AAr[MDIM*MDIM], g_AAi[MDIM*MDIM];
__device__ float2 g_At2[MDIM*NMEAS];                     // (Ar,Ai), [m][n]
__device__ float g_D[MDIM];
__device__ float g_AYr[BATCH*MDIM], g_AYi[BATCH*MDIM];
__device__ float g_F1[32*MDIM*BATCH];                    // conv1 out, [oc][h=m][w=b]
__device__ float g_fmp[2*64*BATCH];                      // partial means, [half][oc][b]
__device__ float g_c[BATCH*9], g_d[BATCH*9], g_T[BATCH*10];
__device__ float g_Ur[2][BATCH*MDIM], g_Ui[2][BATCH*MDIM];
__device__ float g_Lam[BATCH*MDIM];
__device__ float g_eps[BATCH];
__device__ unsigned int g_max;

extern __shared__ float sm2[];

// ---------------- K0: AA = A^H A, D, At2 ----------
__global__ void k_prep(const float* __restrict__ Ar, const float* __restrict__ Ai) {
    int i = blockIdx.x, j = threadIdx.x;
    __shared__ float cr[NMEAS], ci[NMEAS];
    if (j < NMEAS) { cr[j] = Ar[j*MDIM + i]; ci[j] = Ai[j*MDIM + i]; }
    __syncthreads();
    float sr = 0.f, si = 0.f;
    for (int n = 0; n < NMEAS; n++) {
        float arj = Ar[n*MDIM + j], aij = Ai[n*MDIM + j];
        sr += cr[n]*arj + ci[n]*aij;
        si += cr[n]*aij - ci[n]*arj;
    }
    g_AAr[i*MDIM + j] = sr;
    g_AAi[i*MDIM + j] = si;
    if (j == i) g_D[i] = sr;
    if (j < NMEAS) g_At2[i*NMEAS + j] = make_float2(cr[j], ci[j]);
    if (i == 0 && j == 0) g_max = 0u;
}

// ---------------- K1: AY = A^H Y ----------------------
__global__ void k_ay(const float* __restrict__ Yr, const float* __restrict__ Yi,
                     const float* __restrict__ Ar, const float* __restrict__ Ai) {
    int b0 = blockIdx.x * 8;
    __shared__ float sYr[8][NMEAS], sYi[8][NMEAS];
    for (int idx = threadIdx.x; idx < 8*NMEAS; idx += 256) {
        int bl = idx >> 7, n = idx & 127;
        sYr[bl][n] = Yr[(b0 + bl)*NMEAS + n];
        sYi[bl][n] = Yi[(b0 + bl)*NMEAS + n];
    }
    __syncthreads();
    int m = threadIdx.x;
    float ayr[8], ayi[8];
    #pragma unroll
    for (int q = 0; q < 8; q++) { ayr[q] = 0.f; ayi[q] = 0.f; }
    for (int n = 0; n < NMEAS; n++) {
        float ar = Ar[n*MDIM + m], ai = Ai[n*MDIM + m];
        #pragma unroll
        for (int q = 0; q < 8; q++) {
            float yr = sYr[q][n], yi = sYi[q][n];
            ayr[q] += ar*yr + ai*yi;
            ayi[q] += ar*yi - ai*yr;
        }
    }
    #pragma unroll
    for (int q = 0; q < 8; q++) {
        g_AYr[(b0 + q)*MDIM + m] = ayr[q];
        g_AYi[(b0 + q)*MDIM + m] = ayi[q];
    }
}

// ---------------- K2: conv1 (2->32, 3x3) + relu -------------------
__global__ void k_conv1(const float* __restrict__ w1, const float* __restrict__ b1) {
    int w0 = blockIdx.x * 32, h0 = blockIdx.y * 8;
    __shared__ float xs[2][10][34];
    __shared__ float ws[576];
    __shared__ float bs[32];
    int tid = threadIdx.x;
    for (int idx = tid; idx < 680; idx += 256) {
        int ic = idx / 340, r = idx % 340, hl = r / 34, wl = r % 34;
        int h = h0 - 1 + hl, w = w0 - 1 + wl;
        float v = 0.f;
        if (h >= 0 && h < MDIM && w >= 0 && w < BATCH)
            v = ic ? g_AYi[w*MDIM + h] : g_AYr[w*MDIM + h];
        xs[ic][hl][wl] = v;
    }
    for (int idx = tid; idx < 576; idx += 256) ws[idx] = w1[idx];
    if (tid < 32) bs[tid] = b1[tid];
    __syncthreads();
    int hl = tid / 32, wl = tid % 32;
    float xv[18];
    #pragma unroll
    for (int ic = 0; ic < 2; ic++)
        #pragma unroll
        for (int kh = 0; kh < 3; kh++)
            #pragma unroll
            for (int kw = 0; kw < 3; kw++)
                xv[ic*9 + kh*3 + kw] = xs[ic][hl + kh][wl + kw];
    int h = h0 + hl, w = w0 + wl;
    for (int oc = 0; oc < 32; oc++) {
        float a = bs[oc];
        #pragma unroll
        for (int t = 0; t < 18; t++) a += xv[t] * ws[oc*18 + t];
        g_F1[(oc*MDIM + h)*BATCH + w] = fmaxf(a, 0.f);
    }
}

// ---------------- K3: conv2 (32->64) + relu + partial mean --------
// pre-paired data smem: px[ic][wll][t] = (x[hb-1+t], x[hb+7+t]), pitch 11
#define CPITCH 11
__global__ __launch_bounds__(256) void k_conv2(const float* __restrict__ w2,
                                               const float* __restrict__ b2) {
    float* wsm = sm2;                          // 18432 floats
    float2* px = (float2*)(sm2 + 18432);       // 32*18*11 float2
    __shared__ float bs[64];
    int tid = threadIdx.x;
    int w0 = blockIdx.x * 16;
    int by = blockIdx.y;
    for (int idx = tid; idx < 18432; idx += 256) wsm[idx] = w2[idx];
    if (tid < 64) bs[tid] = b2[tid];
    int wl = tid & 15, og = tid >> 4;
    int ocb = og * 4;
    float sum4[4] = {0.f, 0.f, 0.f, 0.f};
    for (int hc = 0; hc < 8; hc++) {
        int hb = by*128 + hc*16;
        __syncthreads();
        for (int idx = tid; idx < 5760; idx += 256) {
            int ic = idx / 180, r = idx % 180, t = r / 18, wll = r % 18;
            int h1 = hb - 1 + t, h2 = h1 + 8;
            int w = w0 - 1 + wll;
            bool wok = (w >= 0 && w < BATCH);
            const float* base = g_F1 + (size_t)ic*MDIM*BATCH + w;
            float v1 = (wok && h1 >= 0 && h1 < MDIM) ? base[(size_t)h1*BATCH] : 0.f;
            float v2 = (wok && h2 < MDIM)            ? base[(size_t)h2*BATCH] : 0.f;
            px[(ic*18 + wll)*CPITCH + t] = make_float2(v1, v2);
        }
        __syncthreads();
        ull acc[4][8];
        #pragma unroll
        for (int o = 0; o < 4; o++) {
            ull bias2 = pk2(bs[ocb + o], bs[ocb + o]);
            #pragma unroll
            for (int p = 0; p < 8; p++) acc[o][p] = bias2;
        }
        for (int ic = 0; ic < 32; ic++) {
            const float2* pb = px + (ic*18 + wl)*CPITCH;
            const float* wb = wsm + ocb*288 + ic*9;
            #pragma unroll
            for (int kw = 0; kw < 3; kw++) {
                const float2* pp = pb + kw*CPITCH;
                ull xp[10];
                #pragma unroll
                for (int t = 0; t < 10; t++) xp[t] = *(const ull*)(pp + t);
                #pragma unroll
                for (int kh = 0; kh < 3; kh++) {
                    ull wp[4];
                    #pragma unroll
                    for (int o = 0; o < 4; o++) {
                        float wv = wb[o*288 + kh*3 + kw];
                        wp[o] = pk2(wv, wv);
                    }
                    #pragma unroll
                    for (int p = 0; p < 8; p++) {
                        fma2(acc[0][p], wp[0], xp[p + kh]);
                        fma2(acc[1][p], wp[1], xp[p + kh]);
                        fma2(acc[2][p], wp[2], xp[p + kh]);
                        fma2(acc[3][p], wp[3], xp[p + kh]);
                    }
                }
            }
        }
        #pragma unroll
        for (int o = 0; o < 4; o++)
            #pragma unroll
            for (int p = 0; p < 8; p++) {
                float2 v = upk2(acc[o][p]);
                sum4[o] += fmaxf(v.x, 0.f) + fmaxf(v.y, 0.f);
            }
    }
    #pragma unroll
    for (int o = 0; o < 4; o++)
        g_fmp[(by*64 + ocb + o)*BATCH + w0 + wl] = sum4[o] * (1.f / 256.f);
}

// ---------------- K4: conv1d heads, one pass, f cached in smem ------------
__global__ __launch_bounds__(128) void k_heads(
        const float* __restrict__ hcw, const float* __restrict__ hcb,
        const float* __restrict__ hdw, const float* __restrict__ hdb,
        const float* __restrict__ hTw, const float* __restrict__ hTb) {
    float* sf = sm2;              // 64 * 130
    float* sw = sm2 + 64*130;     // 28 * 192
    __shared__ float sb[28];
    int tid = threadIdx.x;
    int b0 = blockIdx.x * 128;
    for (int idx = tid; idx < 64*130; idx += 128) {
        int ic = idx / 130, off = idx % 130;
        int b = b0 - 1 + off;
        float v = 0.f;
        if (b >= 0 && b < BATCH) v = g_fmp[ic*BATCH + b] + g_fmp[(64 + ic)*BATCH + b];
        sf[idx] = v;
    }
    for (int idx = tid; idx < 28*192; idx += 128) {
        int l = idx / 192, r = idx % 192;
        sw[idx] = (l < 9) ? hcw[l*192 + r] : (l < 18) ? hdw[(l-9)*192 + r] : hTw[(l-18)*192 + r];
    }
    if (tid < 28) sb[tid] = (tid < 9) ? hcb[tid] : (tid < 18) ? hdb[tid-9] : hTb[tid-18];
    __syncthreads();
    float acc[28];
    #pragma unroll
    for (int l = 0; l < 28; l++) acc[l] = sb[l];
    for (int ic = 0; ic < 64; ic++) {
        float x0 = sf[ic*130 + tid];
        float x1 = sf[ic*130 + tid + 1];
        float x2 = sf[ic*130 + tid + 2];
        #pragma unroll
        for (int l = 0; l < 28; l++) {
            const float* w = sw + l*192 + ic*3;
            acc[l] += w[0]*x0 + w[1]*x1 + w[2]*x2;
        }
    }
    int b = b0 + tid;
    #pragma unroll
    for (int l = 0; l < 28; l++) {
        float v = fabsf(acc[l]);
        if (l < 9)       { v = fminf(fmaxf(v, 1e-6f), 100.f); g_c[b*9 + l] = v; }
        else if (l < 18) { v = fmaxf(v, 1e-6f);               g_d[b*9 + (l-9)] = v; }
        else             { v = fminf(fmaxf(v, 1e-6f), 100.f); g_T[b*10 + (l-18)] = v; }
    }
}

// ---------------- K5: init ----------------------------------------
__global__ void k_init(const float* __restrict__ a0, const float* __restrict__ b0) {
    int b = blockIdx.x, m = threadIdx.x;
    if (m == 0) g_eps[b] = a0[0] / b0[0];
    float lam = g_c[b*9] / g_d[b*9];
    g_Lam[b*MDIM + m] = lam;
    g_Ur[0][b*MDIM + m] = 0.f;
    g_Ui[0][b*MDIM + m] = 0.f;
}

// ---------------- K6: fused AA@U GEMM + U update (f32x2, prepacked smem) ---
// 64b x 64i tile, 256 threads, 4b x 4i per thread. smem rows pitch 17 ull.
#define GP 17
__global__ __launch_bounds__(256) void k_gemmU(int k, int src, int dst) {
    __shared__ ull sU2[64*GP], sUs[64*GP], sA2[64*GP];
    int tid = threadIdx.x;
    int b0 = blockIdx.x * 64, i0 = blockIdx.y * 64;
    int tx = tid & 15, ty = tid >> 4;
    ull acc[4][4];
    #pragma unroll
    for (int u = 0; u < 4; u++)
        #pragma unroll
        for (int v = 0; v < 4; v++) acc[u][v] = 0ull;
    const float* Urp = g_Ur[src];
    const float* Uip = g_Ui[src];
    for (int jc = 0; jc < MDIM; jc += 16) {
        __syncthreads();
        #pragma unroll
        for (int it = 0; it < 4; it++) {
            int idx = tid + it*256;
            int l = idx >> 4, jl = idx & 15;
            float ur = Urp[(b0 + l)*MDIM + jc + jl];
            float ui = Uip[(b0 + l)*MDIM + jc + jl];
            sU2[l*GP + jl] = pk2(ur, ui);
            sUs[l*GP + jl] = pk2(-ui, ur);
            float ar = g_AAr[(i0 + l)*MDIM + jc + jl];
            float ai = g_AAi[(i0 + l)*MDIM + jc + jl];
            sA2[l*GP + jl] = pk2(ar, ai);
        }
        __syncthreads();
        #pragma unroll 4
        for (int j = 0; j < 16; j++) {
            ull u2[4], us[4];
            #pragma unroll
            for (int u = 0; u < 4; u++) {
                u2[u] = sU2[(ty + 16*u)*GP + j];
                us[u] = sUs[(ty + 16*u)*GP + j];
            }
            #pragma unroll
            for (int v = 0; v < 4; v++) {
                float2 a = upk2(sA2[(tx + 16*v)*GP + j]);
                ull arr = pk2(a.x, a.x);
                ull aii = pk2(a.y, a.y);
                #pragma unroll
                for (int u = 0; u < 4; u++) {
                    fma2(acc[u][v], arr, u2[u]);
                    fma2(acc[u][v], aii, us[u]);
                }
            }
        }
    }
    #pragma unroll
    for (int u = 0; u < 4; u++) {
        int b = b0 + ty + 16*u;
        float Tk = g_T[b*10 + k], e = g_eps[b];
        #pragma unroll
        for (int v = 0; v < 4; v++) {
            int i = i0 + tx + 16*v;
            float lam = g_Lam[b*MDIM + i];
            float uor = Urp[b*MDIM + i], uoi = Uip[b*MDIM + i];
            float inv = e / (e*Tk + lam + 1e-6f);
            float2 cc = upk2(acc[u][v]);
            g_Ur[dst][b*MDIM + i] = inv * (Tk*uor - cc.x + g_AYr[b*MDIM + i]);
            g_Ui[dst][b*MDIM + i] = inv * (Tk*uoi - cc.y + g_AYi[b*MDIM + i]);
        }
    }
}

// ---------------- K8: residual + eps1 + Sigma/eps2 + eps + Lam (fused) -----
__global__ __launch_bounds__(256) void k_post(int k, int dst,
                       const float* __restrict__ Yr, const float* __restrict__ Yi,
                       const float* __restrict__ a0p, const float* __restrict__ b0p) {
    int b0 = blockIdx.x * 8;
    int tid = threadIdx.x;
    __shared__ ull sU2[8][256], sUs[8][256];
    __shared__ float sq[8][128];
    __shared__ float seps1[8];
    __shared__ float se[8];
    __shared__ float seps2s[8][8];
    const float* Urp = g_Ur[dst];
    const float* Uip = g_Ui[dst];
    if (tid < 8) se[tid] = g_eps[b0 + tid];
    for (int idx = tid; idx < 8*MDIM; idx += 256) {
        int bl = idx >> 8, m = idx & 255;
        float ur = Urp[(b0 + bl)*MDIM + m];
        float ui = Uip[(b0 + bl)*MDIM + m];
        sU2[bl][m] = pk2(ur, ui);
        sUs[bl][m] = pk2(-ui, ur);
    }
    __syncthreads();
    int n = tid & 127, g = tid >> 7;
    ull m2[4] = {0ull, 0ull, 0ull, 0ull};
    #pragma unroll 2
    for (int m = 0; m < MDIM; m++) {
        float2 a2 = g_At2[m*NMEAS + n];
        ull arr = pk2(a2.x, a2.x);
        ull aii = pk2(a2.y, a2.y);
        #pragma unroll
        for (int q = 0; q < 4; q++) {
            fma2(m2[q], arr, sU2[g*4 + q][m]);
            fma2(m2[q], aii, sUs[g*4 + q][m]);
        }
    }
    #pragma unroll
    for (int q = 0; q < 4; q++) {
        int bb = g*4 + q;
        float2 au = upk2(m2[q]);
        float rr = Yr[(b0 + bb)*NMEAS + n] - au.x;
        float ri = Yi[(b0 + bb)*NMEAS + n] - au.y;
        sq[bb][n] = rr*rr + ri*ri;
    }
    __syncthreads();
    {
        int wq = tid >> 5, lane = tid & 31;
        float s = sq[wq][lane] + sq[wq][lane + 32] + sq[wq][lane + 64] + sq[wq][lane + 96];
        #pragma unroll
        for (int o = 16; o > 0; o >>= 1) s += __shfl_down_sync(0xffffffffu, s, o);
        if (lane == 0) seps1[wq] = s;
    }
    float Dm = g_D[tid];
    float e2p[8];
    #pragma unroll
    for (int bl = 0; bl < 8; bl++) {
        int b = b0 + bl;
        float lam = g_Lam[b*MDIM + tid];
        float sig = 1.f / (se[bl]*Dm + lam + 1e-6f);
        float2 uv = upk2(sU2[bl][tid]);
        float ck = g_c[b*9 + k], dk = g_d[b*9 + k];
        g_Lam[b*MDIM + tid] = (ck + 1.f) / (dk + uv.x*uv.x + uv.y*uv.y + sig + 1e-6f);
        e2p[bl] = Dm * sig;
    }
    int lane = tid & 31, wrp = tid >> 5;
    #pragma unroll
    for (int bl = 0; bl < 8; bl++) {
        float v = e2p[bl];
        #pragma unroll
        for (int o = 16; o > 0; o >>= 1) v += __shfl_down_sync(0xffffffffu, v, o);
        if (lane == 0) seps2s[wrp][bl] = v;
    }
    __syncthreads();
    if (tid < 8) {
        float s2 = 0.f;
        #pragma unroll
        for (int w = 0; w < 8; w++) s2 += seps2s[w][tid];
        float a = a0p[0] + (float)NMEAS;
        g_eps[b0 + tid] = a / (b0p[0] + seps1[tid] + s2 + 1e-6f);
    }
}

// ---------------- K9: |U| -> out, global max -------------------------------
__global__ void k_abs(int fin, float* __restrict__ out) {
    int idx = blockIdx.x * 256 + threadIdx.x;
    float ur = g_Ur[fin][idx], ui = g_Ui[fin][idx];
    float v = sqrtf(ur*ur + ui*ui);
    out[idx] = v;
    __shared__ float red[256];
    red[threadIdx.x] = v;
    __syncthreads();
    for (int s = 128; s > 0; s >>= 1) {
        if (threadIdx.x < s) red[threadIdx.x] = fmaxf(red[threadIdx.x], red[threadIdx.x + s]);
        __syncthreads();
    }
    if (threadIdx.x == 0) atomicMax(&g_max, __float_as_uint(red[0]));
}

// ---------------- K10: scale + diagnostic tails ----------------------------
__global__ void k_final(float* __restrict__ out) {
    int bid = blockIdx.x;
    if (bid < BATCH) {
        int idx = bid * 256 + threadIdx.x;
        float mx = __uint_as_float(g_max);
        out[idx] = out[idx] / (mx + 1e-8f);
    } else {
        int t = threadIdx.x;
        int base = BATCH * MDIM;
        if (t < 9)       out[base + t] = g_c[(BATCH - 1)*9 + t];
        else if (t < 18) out[base + t] = g_d[(BATCH - 1)*9 + (t - 9)];
        else if (t < 28) out[base + t] = g_T[(BATCH - 1)*10 + (t - 18)];
    }
}

// ---------------- launch ---------------------------------------------------
extern "C" void kernel_launch(void* const* d_in, const int* in_sizes, int n_in,
                              void* d_out, int out_size) {
    const float* Yr  = (const float*)d_in[0];
    const float* Yi  = (const float*)d_in[1];
    const float* Ar  = (const float*)d_in[2];
    const float* Ai  = (const float*)d_in[3];
    const float* c1w = (const float*)d_in[4];
    const float* c1b = (const float*)d_in[5];
    const float* c2w = (const float*)d_in[6];
    const float* c2b = (const float*)d_in[7];
    const float* hcw = (const float*)d_in[8];
    const float* hcb = (const float*)d_in[9];
    const float* hdw = (const float*)d_in[10];
    const float* hdb = (const float*)d_in[11];
    const float* hTw = (const float*)d_in[12];
    const float* hTb = (const float*)d_in[13];
    const float* a0  = (const float*)d_in[14];
    const float* b0  = (const float*)d_in[15];
    float* out = (float*)d_out;

    int conv2_smem = 18432*4 + 32*18*CPITCH*8;          // 124416
    int heads_smem = (64*130 + 28*192)*4;               // 54784
    cudaFuncSetAttribute(k_conv2, cudaFuncAttributeMaxDynamicSharedMemorySize, conv2_smem);
    cudaFuncSetAttribute(k_heads, cudaFuncAttributeMaxDynamicSharedMemorySize, heads_smem);

    k_prep<<<256, 256>>>(Ar, Ai);
    k_ay<<<256, 256>>>(Yr, Yi, Ar, Ai);
    k_conv1<<<dim3(64, 32), 256>>>(c1w, c1b);
    k_conv2<<<dim3(128, 2), 256, conv2_smem>>>(c2w, c2b);
    k_heads<<<16, 128, heads_smem>>>(hcw, hcb, hdw, hdb, hTw, hTb);
    k_init<<<BATCH, 256>>>(a0, b0);

    int src = 0;
    for (int k = 0; k < LNUM - 1; k++) {
        int dst = 1 - src;
        k_gemmU<<<dim3(32, 4), 256>>>(k, src, dst);
        k_post<<<256, 256>>>(k, dst, Yr, Yi, a0, b0);
        src = dst;
    }
    int dst = 1 - src;
    k_gemmU<<<dim3(32, 4), 256>>>(LNUM - 1, src, dst);
    k_abs<<<2048, 256>>>(dst, out);
    k_final<<<2049, 256>>>(out);
}

// round 4
// speedup vs baseline: 1.2816x; 1.0420x over previous
#include <cuda_runtime.h>
#include <math.h>

#define BATCH 2048
#define NMEAS 128
#define MDIM  256
#define LNUM  10

typedef unsigned long long ull;

__device__ __forceinline__ ull pk2(float x, float y) {
    ull r; asm("mov.b64 %0, {%1, %2};" : "=l"(r) : "f"(x), "f"(y)); return r;
}
__device__ __forceinline__ float2 upk2(ull v) {
    float2 t; asm("mov.b64 {%0, %1}, %2;" : "=f"(t.x), "=f"(t.y) : "l"(v)); return t;
}
__device__ __forceinline__ void fma2(ull& d, ull a, ull b) {
    asm("fma.rn.f32x2 %0, %1, %2, %3;" : "=l"(d) : "l"(a), "l"(b), "l"(d));
}

// ---------------- scratch ----------------
__device__ float g_AAr[MDIM*MDIM], g_AAi[MDIM*MDIM];
__device__ float2 g_At2[MDIM*NMEAS];
__device__ float g_D[MDIM];
__device__ float g_AYr[BATCH*MDIM], g_AYi[BATCH*MDIM];
__device__ float g_F1[32*MDIM*BATCH];
__device__ float g_fmp[2*64*BATCH];
__device__ float g_c[BATCH*9], g_d[BATCH*9], g_T[BATCH*10];
__device__ float g_Ur[2][BATCH*MDIM], g_Ui[2][BATCH*MDIM];
__device__ float g_Lam[BATCH*MDIM];
__device__ float g_eps[BATCH];
__device__ unsigned int g_max;

extern __shared__ float sm2[];

// ---------------- K0: AA = A^H A, D, At2 ----------
__global__ void k_prep(const float* __restrict__ Ar, const float* __restrict__ Ai) {
    int i = blockIdx.x, j = threadIdx.x;
    __shared__ float cr[NMEAS], ci[NMEAS];
    if (j < NMEAS) { cr[j] = Ar[j*MDIM + i]; ci[j] = Ai[j*MDIM + i]; }
    __syncthreads();
    float sr = 0.f, si = 0.f;
    for (int n = 0; n < NMEAS; n++) {
        float arj = Ar[n*MDIM + j], aij = Ai[n*MDIM + j];
        sr += cr[n]*arj + ci[n]*aij;
        si += cr[n]*aij - ci[n]*arj;
    }
    g_AAr[i*MDIM + j] = sr;
    g_AAi[i*MDIM + j] = si;
    if (j == i) g_D[i] = sr;
    if (j < NMEAS) g_At2[i*NMEAS + j] = make_float2(cr[j], ci[j]);
    if (i == 0 && j == 0) g_max = 0u;
}

// ---------------- K1: AY = A^H Y ----------------------
__global__ void k_ay(const float* __restrict__ Yr, const float* __restrict__ Yi,
                     const float* __restrict__ Ar, const float* __restrict__ Ai) {
    int b0 = blockIdx.x * 8;
    __shared__ float sYr[8][NMEAS], sYi[8][NMEAS];
    for (int idx = threadIdx.x; idx < 8*NMEAS; idx += 256) {
        int bl = idx >> 7, n = idx & 127;
        sYr[bl][n] = Yr[(b0 + bl)*NMEAS + n];
        sYi[bl][n] = Yi[(b0 + bl)*NMEAS + n];
    }
    __syncthreads();
    int m = threadIdx.x;
    float ayr[8], ayi[8];
    #pragma unroll
    for (int q = 0; q < 8; q++) { ayr[q] = 0.f; ayi[q] = 0.f; }
    for (int n = 0; n < NMEAS; n++) {
        float ar = Ar[n*MDIM + m], ai = Ai[n*MDIM + m];
        #pragma unroll
        for (int q = 0; q < 8; q++) {
            float yr = sYr[q][n], yi = sYi[q][n];
            ayr[q] += ar*yr + ai*yi;
            ayi[q] += ar*yi - ai*yr;
        }
    }
    #pragma unroll
    for (int q = 0; q < 8; q++) {
        g_AYr[(b0 + q)*MDIM + m] = ayr[q];
        g_AYi[(b0 + q)*MDIM + m] = ayi[q];
    }
}

// ---------------- K2: conv1 (2->32, 3x3) + relu -------------------
__global__ void k_conv1(const float* __restrict__ w1, const float* __restrict__ b1) {
    int w0 = blockIdx.x * 32, h0 = blockIdx.y * 8;
    __shared__ float xs[2][10][34];
    __shared__ float ws[576];
    __shared__ float bs[32];
    int tid = threadIdx.x;
    for (int idx = tid; idx < 680; idx += 256) {
        int ic = idx / 340, r = idx % 340, hl = r / 34, wl = r % 34;
        int h = h0 - 1 + hl, w = w0 - 1 + wl;
        float v = 0.f;
        if (h >= 0 && h < MDIM && w >= 0 && w < BATCH)
            v = ic ? g_AYi[w*MDIM + h] : g_AYr[w*MDIM + h];
        xs[ic][hl][wl] = v;
    }
    for (int idx = tid; idx < 576; idx += 256) ws[idx] = w1[idx];
    if (tid < 32) bs[tid] = b1[tid];
    __syncthreads();
    int hl = tid / 32, wl = tid % 32;
    float xv[18];
    #pragma unroll
    for (int ic = 0; ic < 2; ic++)
        #pragma unroll
        for (int kh = 0; kh < 3; kh++)
            #pragma unroll
            for (int kw = 0; kw < 3; kw++)
                xv[ic*9 + kh*3 + kw] = xs[ic][hl + kh][wl + kw];
    int h = h0 + hl, w = w0 + wl;
    for (int oc = 0; oc < 32; oc++) {
        float a = bs[oc];
        #pragma unroll
        for (int t = 0; t < 18; t++) a += xv[t] * ws[oc*18 + t];
        g_F1[(oc*MDIM + h)*BATCH + w] = fmaxf(a, 0.f);
    }
}

// ---------------- K3: conv2 (32->64) + relu + partial mean --------
// grid (128 w-tiles, 2 h-halves, 2 oc-halves). 2 blocks/SM.
#define CPITCH 11
__global__ __launch_bounds__(256) void k_conv2(const float* __restrict__ w2,
                                               const float* __restrict__ b2) {
    float* wsm = sm2;                          // 9216 floats (32 oc)
    float2* px = (float2*)(sm2 + 9216);        // 32*18*11 float2
    __shared__ float bs[32];
    int tid = threadIdx.x;
    int w0 = blockIdx.x * 16;
    int by = blockIdx.y;
    int oz = blockIdx.z;
    for (int idx = tid; idx < 9216; idx += 256) wsm[idx] = w2[oz*9216 + idx];
    if (tid < 32) bs[tid] = b2[oz*32 + tid];
    int wl = tid & 15, og = tid >> 4;
    int o0 = og, o1 = og + 16;
    float sum2[2] = {0.f, 0.f};
    for (int hc = 0; hc < 8; hc++) {
        int hb = by*128 + hc*16;
        __syncthreads();
        for (int idx = tid; idx < 5760; idx += 256) {
            int ic = idx / 180, r = idx % 180, t = r / 18, wll = r % 18;
            int h1 = hb - 1 + t, h2 = h1 + 8;
            int w = w0 - 1 + wll;
            bool wok = (w >= 0 && w < BATCH);
            const float* base = g_F1 + (size_t)ic*MDIM*BATCH + w;
            float v1 = (wok && h1 >= 0 && h1 < MDIM) ? base[(size_t)h1*BATCH] : 0.f;
            float v2 = (wok && h2 < MDIM)            ? base[(size_t)h2*BATCH] : 0.f;
            px[(ic*18 + wll)*CPITCH + t] = make_float2(v1, v2);
        }
        __syncthreads();
        ull acc[2][8];
        {
            ull b0p = pk2(bs[o0], bs[o0]);
            ull b1p = pk2(bs[o1], bs[o1]);
            #pragma unroll
            for (int p = 0; p < 8; p++) { acc[0][p] = b0p; acc[1][p] = b1p; }
        }
        for (int ic = 0; ic < 32; ic++) {
            const float2* pb = px + (ic*18 + wl)*CPITCH;
            const float* wb = wsm + ic*9;
            #pragma unroll
            for (int kw = 0; kw < 3; kw++) {
                const float2* pp = pb + kw*CPITCH;
                ull xp[10];
                #pragma unroll
                for (int t = 0; t < 10; t++) xp[t] = *(const ull*)(pp + t);
                #pragma unroll
                for (int kh = 0; kh < 3; kh++) {
                    float wv0 = wb[o0*288 + kh*3 + kw];
                    float wv1 = wb[o1*288 + kh*3 + kw];
                    ull wp0 = pk2(wv0, wv0);
                    ull wp1 = pk2(wv1, wv1);
                    #pragma unroll
                    for (int p = 0; p < 8; p++) {
                        fma2(acc[0][p], wp0, xp[p + kh]);
                        fma2(acc[1][p], wp1, xp[p + kh]);
                    }
                }
            }
        }
        #pragma unroll
        for (int o = 0; o < 2; o++)
            #pragma unroll
            for (int p = 0; p < 8; p++) {
                float2 v = upk2(acc[o][p]);
                sum2[o] += fmaxf(v.x, 0.f) + fmaxf(v.y, 0.f);
            }
    }
    g_fmp[(by*64 + oz*32 + o0)*BATCH + w0 + wl] = sum2[0] * (1.f / 256.f);
    g_fmp[(by*64 + oz*32 + o1)*BATCH + w0 + wl] = sum2[1] * (1.f / 256.f);
}

// ---------------- K4: conv1d heads, one pass, f cached in smem ------------
__global__ __launch_bounds__(128) void k_heads(
        const float* __restrict__ hcw, const float* __restrict__ hcb,
        const float* __restrict__ hdw, const float* __restrict__ hdb,
        const float* __restrict__ hTw, const float* __restrict__ hTb) {
    float* sf = sm2;              // 64 * 130
    float* sw = sm2 + 64*130;     // 28 * 192
    __shared__ float sb[28];
    int tid = threadIdx.x;
    int b0 = blockIdx.x * 128;
    for (int idx = tid; idx < 64*130; idx += 128) {
        int ic = idx / 130, off = idx % 130;
        int b = b0 - 1 + off;
        float v = 0.f;
        if (b >= 0 && b < BATCH) v = g_fmp[ic*BATCH + b] + g_fmp[(64 + ic)*BATCH + b];
        sf[idx] = v;
    }
    for (int idx = tid; idx < 28*192; idx += 128) {
        int l = idx / 192, r = idx % 192;
        sw[idx] = (l < 9) ? hcw[l*192 + r] : (l < 18) ? hdw[(l-9)*192 + r] : hTw[(l-18)*192 + r];
    }
    if (tid < 28) sb[tid] = (tid < 9) ? hcb[tid] : (tid < 18) ? hdb[tid-9] : hTb[tid-18];
    __syncthreads();
    float acc[28];
    #pragma unroll
    for (int l = 0; l < 28; l++) acc[l] = sb[l];
    for (int ic = 0; ic < 64; ic++) {
        float x0 = sf[ic*130 + tid];
        float x1 = sf[ic*130 + tid + 1];
        float x2 = sf[ic*130 + tid + 2];
        #pragma unroll
        for (int l = 0; l < 28; l++) {
            const float* w = sw + l*192 + ic*3;
            acc[l] += w[0]*x0 + w[1]*x1 + w[2]*x2;
        }
    }
    int b = b0 + tid;
    #pragma unroll
    for (int l = 0; l < 28; l++) {
        float v = fabsf(acc[l]);
        if (l < 9)       { v = fminf(fmaxf(v, 1e-6f), 100.f); g_c[b*9 + l] = v; }
        else if (l < 18) { v = fmaxf(v, 1e-6f);               g_d[b*9 + (l-9)] = v; }
        else             { v = fminf(fmaxf(v, 1e-6f), 100.f); g_T[b*10 + (l-18)] = v; }
    }
}

// ---------------- K5: init ----------------------------------------
__global__ void k_init(const float* __restrict__ a0, const float* __restrict__ b0) {
    int b = blockIdx.x, m = threadIdx.x;
    if (m == 0) g_eps[b] = a0[0] / b0[0];
    float lam = g_c[b*9] / g_d[b*9];
    g_Lam[b*MDIM + m] = lam;
    g_Ur[0][b*MDIM + m] = 0.f;
    g_Ui[0][b*MDIM + m] = 0.f;
}

// ---------------- K6: fused AA@U GEMM + U update (pipelined prefetch) ------
#define GP 17
__global__ __launch_bounds__(256) void k_gemmU(int k, int src, int dst) {
    __shared__ ull sU2[64*GP], sUs[64*GP], sA2[64*GP];
    int tid = threadIdx.x;
    int b0 = blockIdx.x * 64, i0 = blockIdx.y * 64;
    int tx = tid & 15, ty = tid >> 4;
    int lrow = tid >> 2, lc = (tid & 3) * 4;
    const float* Urp = g_Ur[src];
    const float* Uip = g_Ui[src];
    float4 fUr = *(const float4*)&Urp[(b0 + lrow)*MDIM + lc];
    float4 fUi = *(const float4*)&Uip[(b0 + lrow)*MDIM + lc];
    float4 fAr = *(const float4*)&g_AAr[(i0 + lrow)*MDIM + lc];
    float4 fAi = *(const float4*)&g_AAi[(i0 + lrow)*MDIM + lc];
    ull acc[4][4];
    #pragma unroll
    for (int u = 0; u < 4; u++)
        #pragma unroll
        for (int v = 0; v < 4; v++) acc[u][v] = 0ull;
    for (int jc = 0; jc < MDIM; jc += 16) {
        __syncthreads();
        {
            float ur[4] = {fUr.x, fUr.y, fUr.z, fUr.w};
            float ui[4] = {fUi.x, fUi.y, fUi.z, fUi.w};
            float ar[4] = {fAr.x, fAr.y, fAr.z, fAr.w};
            float ai[4] = {fAi.x, fAi.y, fAi.z, fAi.w};
            #pragma unroll
            for (int t = 0; t < 4; t++) {
                sU2[lrow*GP + lc + t] = pk2(ur[t], ui[t]);
                sUs[lrow*GP + lc + t] = pk2(-ui[t], ur[t]);
                sA2[lrow*GP + lc + t] = pk2(ar[t], ai[t]);
            }
        }
        __syncthreads();
        if (jc + 16 < MDIM) {
            int c = jc + 16 + lc;
            fUr = *(const float4*)&Urp[(b0 + lrow)*MDIM + c];
            fUi = *(const float4*)&Uip[(b0 + lrow)*MDIM + c];
            fAr = *(const float4*)&g_AAr[(i0 + lrow)*MDIM + c];
            fAi = *(const float4*)&g_AAi[(i0 + lrow)*MDIM + c];
        }
        #pragma unroll 4
        for (int j = 0; j < 16; j++) {
            ull u2[4], us[4];
            #pragma unroll
            for (int u = 0; u < 4; u++) {
                u2[u] = sU2[(ty + 16*u)*GP + j];
                us[u] = sUs[(ty + 16*u)*GP + j];
            }
            #pragma unroll
            for (int v = 0; v < 4; v++) {
                float2 a = upk2(sA2[(tx + 16*v)*GP + j]);
                ull arr = pk2(a.x, a.x);
                ull aii = pk2(a.y, a.y);
                #pragma unroll
                for (int u = 0; u < 4; u++) {
                    fma2(acc[u][v], arr, u2[u]);
                    fma2(acc[u][v], aii, us[u]);
                }
            }
        }
    }
    #pragma unroll
    for (int u = 0; u < 4; u++) {
        int b = b0 + ty + 16*u;
        float Tk = g_T[b*10 + k], e = g_eps[b];
        #pragma unroll
        for (int v = 0; v < 4; v++) {
            int i = i0 + tx + 16*v;
            float lam = g_Lam[b*MDIM + i];
            float uor = Urp[b*MDIM + i], uoi = Uip[b*MDIM + i];
            float inv = e / (e*Tk + lam + 1e-6f);
            float2 cc = upk2(acc[u][v]);
            g_Ur[dst][b*MDIM + i] = inv * (Tk*uor - cc.x + g_AYr[b*MDIM + i]);
            g_Ui[dst][b*MDIM + i] = inv * (Tk*uoi - cc.y + g_AYi[b*MDIM + i]);
        }
    }
}

// ---------------- K8: residual + eps1 + Sigma/eps2 + eps + Lam (fused) -----
__global__ __launch_bounds__(256) void k_post(int k, int dst,
                       const float* __restrict__ Yr, const float* __restrict__ Yi,
                       const float* __restrict__ a0p, const float* __restrict__ b0p) {
    int b0 = blockIdx.x * 8;
    int tid = threadIdx.x;
    __shared__ ull sU2[8][256], sUs[8][256];
    __shared__ float sq[8][128];
    __shared__ float seps1[8];
    __shared__ float se[8];
    __shared__ float seps2s[8][8];
    const float* Urp = g_Ur[dst];
    const float* Uip = g_Ui[dst];
    if (tid < 8) se[tid] = g_eps[b0 + tid];
    for (int idx = tid; idx < 8*MDIM; idx += 256) {
        int bl = idx >> 8, m = idx & 255;
        float ur = Urp[(b0 + bl)*MDIM + m];
        float ui = Uip[(b0 + bl)*MDIM + m];
        sU2[bl][m] = pk2(ur, ui);
        sUs[bl][m] = pk2(-ui, ur);
    }
    __syncthreads();
    int n = tid & 127, g = tid >> 7;
    ull m2[4] = {0ull, 0ull, 0ull, 0ull};
    #pragma unroll 2
    for (int m = 0; m < MDIM; m++) {
        float2 a2 = g_At2[m*NMEAS + n];
        ull arr = pk2(a2.x, a2.x);
        ull aii = pk2(a2.y, a2.y);
        #pragma unroll
        for (int q = 0; q < 4; q++) {
            fma2(m2[q], arr, sU2[g*4 + q][m]);
            fma2(m2[q], aii, sUs[g*4 + q][m]);
        }
    }
    #pragma unroll
    for (int q = 0; q < 4; q++) {
        int bb = g*4 + q;
        float2 au = upk2(m2[q]);
        float rr = Yr[(b0 + bb)*NMEAS + n] - au.x;
        float ri = Yi[(b0 + bb)*NMEAS + n] - au.y;
        sq[bb][n] = rr*rr + ri*ri;
    }
    __syncthreads();
    {
        int wq = tid >> 5, lane = tid & 31;
        float s = sq[wq][lane] + sq[wq][lane + 32] + sq[wq][lane + 64] + sq[wq][lane + 96];
        #pragma unroll
        for (int o = 16; o > 0; o >>= 1) s += __shfl_down_sync(0xffffffffu, s, o);
        if (lane == 0) seps1[wq] = s;
    }
    float Dm = g_D[tid];
    float e2p[8];
    #pragma unroll
    for (int bl = 0; bl < 8; bl++) {
        int b = b0 + bl;
        float lam = g_Lam[b*MDIM + tid];
        float sig = 1.f / (se[bl]*Dm + lam + 1e-6f);
        float2 uv = upk2(sU2[bl][tid]);
        float ck = g_c[b*9 + k], dk = g_d[b*9 + k];
        g_Lam[b*MDIM + tid] = (ck + 1.f) / (dk + uv.x*uv.x + uv.y*uv.y + sig + 1e-6f);
        e2p[bl] = Dm * sig;
    }
    int lane = tid & 31, wrp = tid >> 5;
    #pragma unroll
    for (int bl = 0; bl < 8; bl++) {
        float v = e2p[bl];
        #pragma unroll
        for (int o = 16; o > 0; o >>= 1) v += __shfl_down_sync(0xffffffffu, v, o);
        if (lane == 0) seps2s[wrp][bl] = v;
    }
    __syncthreads();
    if (tid < 8) {
        float s2 = 0.f;
        #pragma unroll
        for (int w = 0; w < 8; w++) s2 += seps2s[w][tid];
        float a = a0p[0] + (float)NMEAS;
        g_eps[b0 + tid] = a / (b0p[0] + seps1[tid] + s2 + 1e-6f);
    }
}

// ---------------- K9: |U| -> out, global max -------------------------------
__global__ void k_abs(int fin, float* __restrict__ out) {
    int idx = blockIdx.x * 256 + threadIdx.x;
    float ur = g_Ur[fin][idx], ui = g_Ui[fin][idx];
    float v = sqrtf(ur*ur + ui*ui);
    out[idx] = v;
    __shared__ float red[256];
    red[threadIdx.x] = v;
    __syncthreads();
    for (int s = 128; s > 0; s >>= 1) {
        if (threadIdx.x < s) red[threadIdx.x] = fmaxf(red[threadIdx.x], red[threadIdx.x + s]);
        __syncthreads();
    }
    if (threadIdx.x == 0) atomicMax(&g_max, __float_as_uint(red[0]));
}

// ---------------- K10: scale + diagnostic tails ----------------------------
__global__ void k_final(float* __restrict__ out) {
    int bid = blockIdx.x;
    if (bid < BATCH) {
        int idx = bid * 256 + threadIdx.x;
        float mx = __uint_as_float(g_max);
        out[idx] = out[idx] / (mx + 1e-8f);
    } else {
        int t = threadIdx.x;
        int base = BATCH * MDIM;
        if (t < 9)       out[base + t] = g_c[(BATCH - 1)*9 + t];
        else if (t < 18) out[base + t] = g_d[(BATCH - 1)*9 + (t - 9)];
        else if (t < 28) out[base + t] = g_T[(BATCH - 1)*10 + (t - 18)];
    }
}

// ---------------- launch ---------------------------------------------------
extern "C" void kernel_launch(void* const* d_in, const int* in_sizes, int n_in,
                              void* d_out, int out_size) {
    const float* Yr  = (const float*)d_in[0];
    const float* Yi  = (const float*)d_in[1];
    const float* Ar  = (const float*)d_in[2];
    const float* Ai  = (const float*)d_in[3];
    const float* c1w = (const float*)d_in[4];
    const float* c1b = (const float*)d_in[5];
    const float* c2w = (const float*)d_in[6];
    const float* c2b = (const float*)d_in[7];
    const float* hcw = (const float*)d_in[8];
    const float* hcb = (const float*)d_in[9];
    const float* hdw = (const float*)d_in[10];
    const float* hdb = (const float*)d_in[11];
    const float* hTw = (const float*)d_in[12];
    const float* hTb = (const float*)d_in[13];
    const float* a0  = (const float*)d_in[14];
    const float* b0  = (const float*)d_in[15];
    float* out = (float*)d_out;

    int conv2_smem = 9216*4 + 32*18*CPITCH*8;           // 87552
    int heads_smem = (64*130 + 28*192)*4;               // 54784
    cudaFuncSetAttribute(k_conv2, cudaFuncAttributeMaxDynamicSharedMemorySize, conv2_smem);
    cudaFuncSetAttribute(k_heads, cudaFuncAttributeMaxDynamicSharedMemorySize, heads_smem);

    k_prep<<<256, 256>>>(Ar, Ai);
    k_ay<<<256, 256>>>(Yr, Yi, Ar, Ai);
    k_conv1<<<dim3(64, 32), 256>>>(c1w, c1b);
    k_conv2<<<dim3(128, 2, 2), 256, conv2_smem>>>(c2w, c2b);
    k_heads<<<16, 128, heads_smem>>>(hcw, hcb, hdw, hdb, hTw, hTb);
    k_init<<<BATCH, 256>>>(a0, b0);

    int src = 0;
    for (int k = 0; k < LNUM - 1; k++) {
        int dst = 1 - src;
        k_gemmU<<<dim3(32, 4), 256>>>(k, src, dst);
        k_post<<<256, 256>>>(k, dst, Yr, Yi, a0, b0);
        src = dst;
    }
    int dst = 1 - src;
    k_gemmU<<<dim3(32, 4), 256>>>(LNUM - 1, src, dst);
    k_abs<<<2048, 256>>>(dst, out);
    k_final<<<2049, 256>>>(out);
}

// round 5
// speedup vs baseline: 1.8266x; 1.4252x over previous
#include <cuda_runtime.h>
#include <math.h>

#define BATCH 2048
#define NMEAS 128
#define MDIM  256
#define LNUM  10

typedef unsigned long long ull;

__device__ __forceinline__ ull pk2(float x, float y) {
    ull r; asm("mov.b64 %0, {%1, %2};" : "=l"(r) : "f"(x), "f"(y)); return r;
}
__device__ __forceinline__ float2 upk2(ull v) {
    float2 t; asm("mov.b64 {%0, %1}, %2;" : "=f"(t.x), "=f"(t.y) : "l"(v)); return t;
}
__device__ __forceinline__ void fma2(ull& d, ull a, ull b) {
    asm("fma.rn.f32x2 %0, %1, %2, %3;" : "=l"(d) : "l"(a), "l"(b), "l"(d));
}

// ---------------- scratch ----------------
__device__ float g_AAr[MDIM*MDIM], g_AAi[MDIM*MDIM];
__device__ float g_D[MDIM];
__device__ float g_AYr[BATCH*MDIM], g_AYi[BATCH*MDIM];
__device__ float g_AYtr[MDIM*BATCH], g_AYti[MDIM*BATCH];
__device__ float g_F1[32*MDIM*BATCH];
__device__ float g_fmp[2*64*BATCH];
__device__ float g_c[BATCH*9], g_d[BATCH*9], g_T[BATCH*10];
__device__ float g_Ur[BATCH*MDIM], g_Ui[BATCH*MDIM];
__device__ float g_Wr[BATCH*MDIM], g_Wi[BATCH*MDIM];
__device__ float g_Lam[BATCH*MDIM];
__device__ float g_eps2[BATCH], g_Yn[BATCH];
__device__ unsigned int g_max;

extern __shared__ float sm2[];

// ---------------- K0: AA = A^H A, D ----------
__global__ void k_prep(const float* __restrict__ Ar, const float* __restrict__ Ai) {
    int i = blockIdx.x, j = threadIdx.x;
    __shared__ float cr[NMEAS], ci[NMEAS];
    if (j < NMEAS) { cr[j] = Ar[j*MDIM + i]; ci[j] = Ai[j*MDIM + i]; }
    __syncthreads();
    float sr = 0.f, si = 0.f;
    for (int n = 0; n < NMEAS; n++) {
        float arj = Ar[n*MDIM + j], aij = Ai[n*MDIM + j];
        sr += cr[n]*arj + ci[n]*aij;
        si += cr[n]*aij - ci[n]*arj;
    }
    g_AAr[i*MDIM + j] = sr;
    g_AAi[i*MDIM + j] = si;
    if (j == i) g_D[i] = sr;
    if (i == 0 && j == 0) g_max = 0u;
}

// ---------------- K1: AY = A^H Y (+ transposed copy) ----------------------
__global__ void k_ay(const float* __restrict__ Yr, const float* __restrict__ Yi,
                     const float* __restrict__ Ar, const float* __restrict__ Ai) {
    int b0 = blockIdx.x * 8;
    __shared__ float sYr[8][NMEAS], sYi[8][NMEAS];
    for (int idx = threadIdx.x; idx < 8*NMEAS; idx += 256) {
        int bl = idx >> 7, n = idx & 127;
        sYr[bl][n] = Yr[(b0 + bl)*NMEAS + n];
        sYi[bl][n] = Yi[(b0 + bl)*NMEAS + n];
    }
    __syncthreads();
    int m = threadIdx.x;
    float ayr[8], ayi[8];
    #pragma unroll
    for (int q = 0; q < 8; q++) { ayr[q] = 0.f; ayi[q] = 0.f; }
    for (int n = 0; n < NMEAS; n++) {
        float ar = Ar[n*MDIM + m], ai = Ai[n*MDIM + m];
        #pragma unroll
        for (int q = 0; q < 8; q++) {
            float yr = sYr[q][n], yi = sYi[q][n];
            ayr[q] += ar*yr + ai*yi;
            ayi[q] += ar*yi - ai*yr;
        }
    }
    #pragma unroll
    for (int q = 0; q < 8; q++) {
        g_AYr[(b0 + q)*MDIM + m] = ayr[q];
        g_AYi[(b0 + q)*MDIM + m] = ayi[q];
        g_AYtr[m*BATCH + b0 + q] = ayr[q];
        g_AYti[m*BATCH + b0 + q] = ayi[q];
    }
}

// ---------------- K2: conv1 (2->32, 3x3) + relu, f32x2 h-pairs -------------
// 256 thr = 32 wl x 8 og, OC=4/thread. grid (64 wtiles, 8 hranges of 32)
__global__ __launch_bounds__(256) void k_conv1(const float* __restrict__ w1,
                                               const float* __restrict__ b1) {
    __shared__ float ws[576];
    __shared__ float bs[32];
    __shared__ float2 px[2*34*11];
    int tid = threadIdx.x;
    int w0 = blockIdx.x * 32;
    int hbase = blockIdx.y * 32;
    for (int idx = tid; idx < 576; idx += 256) ws[idx] = w1[idx];
    if (tid < 32) bs[tid] = b1[tid];
    int wl = tid & 31, og = tid >> 5;
    int oc0 = og * 4;
    for (int hc = 0; hc < 2; hc++) {
        int hb = hbase + hc*16;
        __syncthreads();
        for (int idx = tid; idx < 680; idx += 256) {
            int ic = idx / 340, r = idx % 340, wll = r / 10, t = r % 10;
            int h1 = hb - 1 + t, h2 = h1 + 8;
            int w = w0 - 1 + wll;
            bool wok = (w >= 0 && w < BATCH);
            const float* src = ic ? g_AYti : g_AYtr;
            float v1 = (wok && h1 >= 0 && h1 < MDIM) ? src[h1*BATCH + w] : 0.f;
            float v2 = (wok && h2 < MDIM)            ? src[h2*BATCH + w] : 0.f;
            px[(ic*34 + wll)*11 + t] = make_float2(v1, v2);
        }
        __syncthreads();
        ull acc[4][8];
        #pragma unroll
        for (int o = 0; o < 4; o++) {
            ull bp = pk2(bs[oc0 + o], bs[oc0 + o]);
            #pragma unroll
            for (int p = 0; p < 8; p++) acc[o][p] = bp;
        }
        #pragma unroll
        for (int ic = 0; ic < 2; ic++) {
            #pragma unroll
            for (int kw = 0; kw < 3; kw++) {
                const float2* pp = px + (ic*34 + wl + kw)*11;
                ull xp[10];
                #pragma unroll
                for (int t = 0; t < 10; t++) xp[t] = *(const ull*)(pp + t);
                #pragma unroll
                for (int kh = 0; kh < 3; kh++) {
                    ull wp[4];
                    #pragma unroll
                    for (int o = 0; o < 4; o++) {
                        float wv = ws[(oc0 + o)*18 + ic*9 + kh*3 + kw];
                        wp[o] = pk2(wv, wv);
                    }
                    #pragma unroll
                    for (int p = 0; p < 8; p++) {
                        fma2(acc[0][p], wp[0], xp[p + kh]);
                        fma2(acc[1][p], wp[1], xp[p + kh]);
                        fma2(acc[2][p], wp[2], xp[p + kh]);
                        fma2(acc[3][p], wp[3], xp[p + kh]);
                    }
                }
            }
        }
        #pragma unroll
        for (int o = 0; o < 4; o++) {
            int oc = oc0 + o;
            #pragma unroll
            for (int p = 0; p < 8; p++) {
                float2 v = upk2(acc[o][p]);
                g_F1[(oc*MDIM + hb + p)*BATCH + w0 + wl]     = fmaxf(v.x, 0.f);
                g_F1[(oc*MDIM + hb + 8 + p)*BATCH + w0 + wl] = fmaxf(v.y, 0.f);
            }
        }
    }
}

// ---------------- K3: conv2 (32->64) + relu + partial mean, OC=4 -----------
#define CPITCH 11
__global__ __launch_bounds__(128) void k_conv2(const float* __restrict__ w2,
                                               const float* __restrict__ b2) {
    float* wsm = sm2;                          // 32*32*12 = 12288 floats (padded rows)
    float2* px = (float2*)(sm2 + 12288);       // 32*18*11 float2
    __shared__ float bs[32];
    int tid = threadIdx.x;
    int w0 = blockIdx.x * 16;
    int by = blockIdx.y;
    int oz = blockIdx.z;
    for (int idx = tid; idx < 9216; idx += 128) {
        int oc = idx / 288, r = idx % 288, ic = r / 9, t = r % 9;
        wsm[oc*384 + ic*12 + t] = w2[oz*9216 + idx];
    }
    if (tid < 32) bs[tid] = b2[oz*32 + tid];
    int wl = tid & 15, og = tid >> 4;          // og 0..7
    int oc0 = og * 4;
    float sum4[4] = {0.f, 0.f, 0.f, 0.f};
    for (int hc = 0; hc < 8; hc++) {
        int hb = by*128 + hc*16;
        __syncthreads();
        for (int idx = tid; idx < 5760; idx += 128) {
            int ic = idx / 180, r = idx % 180, t = r / 18, wll = r % 18;
            int h1 = hb - 1 + t, h2 = h1 + 8;
            int w = w0 - 1 + wll;
            bool wok = (w >= 0 && w < BATCH);
            const float* base = g_F1 + (size_t)ic*MDIM*BATCH + w;
            float v1 = (wok && h1 >= 0 && h1 < MDIM) ? base[(size_t)h1*BATCH] : 0.f;
            float v2 = (wok && h2 < MDIM)            ? base[(size_t)h2*BATCH] : 0.f;
            px[(ic*18 + wll)*CPITCH + t] = make_float2(v1, v2);
        }
        __syncthreads();
        ull acc[4][8];
        #pragma unroll
        for (int o = 0; o < 4; o++) {
            ull bp = pk2(bs[oc0 + o], bs[oc0 + o]);
            #pragma unroll
            for (int p = 0; p < 8; p++) acc[o][p] = bp;
        }
        for (int ic = 0; ic < 32; ic++) {
            // weights: 3 x float4 per oc (rows padded to 12, 16B-aligned)
            float wv[4][12];
            #pragma unroll
            for (int o = 0; o < 4; o++) {
                const float4* wp4 = (const float4*)&wsm[(oc0 + o)*384 + ic*12];
                float4 a = wp4[0], b = wp4[1], c = wp4[2];
                wv[o][0]=a.x; wv[o][1]=a.y; wv[o][2]=a.z; wv[o][3]=a.w;
                wv[o][4]=b.x; wv[o][5]=b.y; wv[o][6]=b.z; wv[o][7]=b.w;
                wv[o][8]=c.x; wv[o][9]=c.y; wv[o][10]=c.z; wv[o][11]=c.w;
            }
            const float2* pb = px + (ic*18 + wl)*CPITCH;
            #pragma unroll
            for (int kw = 0; kw < 3; kw++) {
                const float2* pp = pb + kw*CPITCH;
                ull xp[10];
                #pragma unroll
                for (int t = 0; t < 10; t++) xp[t] = *(const ull*)(pp + t);
                #pragma unroll
                for (int kh = 0; kh < 3; kh++) {
                    ull wp[4];
                    #pragma unroll
                    for (int o = 0; o < 4; o++)
                        wp[o] = pk2(wv[o][kh*3 + kw], wv[o][kh*3 + kw]);
                    #pragma unroll
                    for (int p = 0; p < 8; p++) {
                        fma2(acc[0][p], wp[0], xp[p + kh]);
                        fma2(acc[1][p], wp[1], xp[p + kh]);
                        fma2(acc[2][p], wp[2], xp[p + kh]);
                        fma2(acc[3][p], wp[3], xp[p + kh]);
                    }
                }
            }
        }
        #pragma unroll
        for (int o = 0; o < 4; o++)
            #pragma unroll
            for (int p = 0; p < 8; p++) {
                float2 v = upk2(acc[o][p]);
                sum4[o] += fmaxf(v.x, 0.f) + fmaxf(v.y, 0.f);
            }
    }
    #pragma unroll
    for (int o = 0; o < 4; o++)
        g_fmp[(by*64 + oz*32 + oc0 + o)*BATCH + w0 + wl] = sum4[o] * (1.f / 256.f);
}

// ---------------- K4: conv1d heads --------------------------------
__global__ __launch_bounds__(128) void k_heads(
        const float* __restrict__ hcw, const float* __restrict__ hcb,
        const float* __restrict__ hdw, const float* __restrict__ hdb,
        const float* __restrict__ hTw, const float* __restrict__ hTb) {
    float* sf = sm2;              // 64 * 130
    float* sw = sm2 + 64*130;     // 28 * 192
    __shared__ float sb[28];
    int tid = threadIdx.x;
    int b0 = blockIdx.x * 128;
    for (int idx = tid; idx < 64*130; idx += 128) {
        int ic = idx / 130, off = idx % 130;
        int b = b0 - 1 + off;
        float v = 0.f;
        if (b >= 0 && b < BATCH) v = g_fmp[ic*BATCH + b] + g_fmp[(64 + ic)*BATCH + b];
        sf[idx] = v;
    }
    for (int idx = tid; idx < 28*192; idx += 128) {
        int l = idx / 192, r = idx % 192;
        sw[idx] = (l < 9) ? hcw[l*192 + r] : (l < 18) ? hdw[(l-9)*192 + r] : hTw[(l-18)*192 + r];
    }
    if (tid < 28) sb[tid] = (tid < 9) ? hcb[tid] : (tid < 18) ? hdb[tid-9] : hTb[tid-18];
    __syncthreads();
    float acc[28];
    #pragma unroll
    for (int l = 0; l < 28; l++) acc[l] = sb[l];
    for (int ic = 0; ic < 64; ic++) {
        float x0 = sf[ic*130 + tid];
        float x1 = sf[ic*130 + tid + 1];
        float x2 = sf[ic*130 + tid + 2];
        #pragma unroll
        for (int l = 0; l < 28; l++) {
            const float* w = sw + l*192 + ic*3;
            acc[l] += w[0]*x0 + w[1]*x1 + w[2]*x2;
        }
    }
    int b = b0 + tid;
    #pragma unroll
    for (int l = 0; l < 28; l++) {
        float v = fabsf(acc[l]);
        if (l < 9)       { v = fminf(fmaxf(v, 1e-6f), 100.f); g_c[b*9 + l] = v; }
        else if (l < 18) { v = fmaxf(v, 1e-6f);               g_d[b*9 + (l-9)] = v; }
        else             { v = fminf(fmaxf(v, 1e-6f), 100.f); g_T[b*10 + (l-18)] = v; }
    }
}

// ---------------- K5: init: Lam, ||Y||^2 ----------------------------------
__global__ void k_init(const float* __restrict__ Yr, const float* __restrict__ Yi) {
    int b = blockIdx.x, i = threadIdx.x;
    __shared__ float sred[8];
    float lam = g_c[b*9] / g_d[b*9];
    g_Lam[b*MDIM + i] = lam;
    float v = 0.f;
    if (i < NMEAS) {
        float yr = Yr[b*NMEAS + i], yi = Yi[b*NMEAS + i];
        v = yr*yr + yi*yi;
    }
    int lane = i & 31, w = i >> 5;
    #pragma unroll
    for (int o = 16; o > 0; o >>= 1) v += __shfl_down_sync(0xffffffffu, v, o);
    if (lane == 0) sred[w] = v;
    __syncthreads();
    if (i == 0) {
        float s = 0.f;
        #pragma unroll
        for (int w2 = 0; w2 < 8; w2++) s += sred[w2];
        g_Yn[b] = s;
    }
}

// ---------------- K6: W = AA @ U (pure GEMM, f32x2, prefetch) --------------
#define GP 17
__global__ __launch_bounds__(256) void k_mm() {
    __shared__ ull sU2[64*GP], sUs[64*GP], sA2[64*GP];
    int tid = threadIdx.x;
    int b0 = blockIdx.x * 64, i0 = blockIdx.y * 64;
    int tx = tid & 15, ty = tid >> 4;
    int lrow = tid >> 2, lc = (tid & 3) * 4;
    float4 fUr = *(const float4*)&g_Ur[(b0 + lrow)*MDIM + lc];
    float4 fUi = *(const float4*)&g_Ui[(b0 + lrow)*MDIM + lc];
    float4 fAr = *(const float4*)&g_AAr[(i0 + lrow)*MDIM + lc];
    float4 fAi = *(const float4*)&g_AAi[(i0 + lrow)*MDIM + lc];
    ull acc[4][4];
    #pragma unroll
    for (int u = 0; u < 4; u++)
        #pragma unroll
        for (int v = 0; v < 4; v++) acc[u][v] = 0ull;
    for (int jc = 0; jc < MDIM; jc += 16) {
        __syncthreads();
        {
            float ur[4] = {fUr.x, fUr.y, fUr.z, fUr.w};
            float ui[4] = {fUi.x, fUi.y, fUi.z, fUi.w};
            float ar[4] = {fAr.x, fAr.y, fAr.z, fAr.w};
            float ai[4] = {fAi.x, fAi.y, fAi.z, fAi.w};
            #pragma unroll
            for (int t = 0; t < 4; t++) {
                sU2[lrow*GP + lc + t] = pk2(ur[t], ui[t]);
                sUs[lrow*GP + lc + t] = pk2(-ui[t], ur[t]);
                sA2[lrow*GP + lc + t] = pk2(ar[t], ai[t]);
            }
        }
        __syncthreads();
        if (jc + 16 < MDIM) {
            int c = jc + 16 + lc;
            fUr = *(const float4*)&g_Ur[(b0 + lrow)*MDIM + c];
            fUi = *(const float4*)&g_Ui[(b0 + lrow)*MDIM + c];
            fAr = *(const float4*)&g_AAr[(i0 + lrow)*MDIM + c];
            fAi = *(const float4*)&g_AAi[(i0 + lrow)*MDIM + c];
        }
        #pragma unroll 4
        for (int j = 0; j < 16; j++) {
            ull u2[4], us[4];
            #pragma unroll
            for (int u = 0; u < 4; u++) {
                u2[u] = sU2[(ty + 16*u)*GP + j];
                us[u] = sUs[(ty + 16*u)*GP + j];
            }
            #pragma unroll
            for (int v = 0; v < 4; v++) {
                float2 a = upk2(sA2[(tx + 16*v)*GP + j]);
                ull arr = pk2(a.x, a.x);
                ull aii = pk2(a.y, a.y);
                #pragma unroll
                for (int u = 0; u < 4; u++) {
                    fma2(acc[u][v], arr, u2[u]);
                    fma2(acc[u][v], aii, us[u]);
                }
            }
        }
    }
    #pragma unroll
    for (int u = 0; u < 4; u++) {
        int b = b0 + ty + 16*u;
        #pragma unroll
        for (int v = 0; v < 4; v++) {
            int i = i0 + tx + 16*v;
            float2 cc = upk2(acc[u][v]);
            g_Wr[b*MDIM + i] = cc.x;
            g_Wi[b*MDIM + i] = cc.y;
        }
    }
}

// ---------------- K7: fused update: eps, Sigma, eps2, U (in place), Lam ----
__global__ __launch_bounds__(256) void k_up(int k,
        const float* __restrict__ a0p, const float* __restrict__ b0p,
        float* __restrict__ out) {
    int b = blockIdx.x, i = threadIdx.x;
    __shared__ float sr1[8];
    __shared__ float sEps;
    int lane = i & 31, w = i >> 5;
    float ur = 0.f, ui = 0.f, wr = 0.f, wi = 0.f;
    if (k > 0) {
        ur = g_Ur[b*MDIM + i]; ui = g_Ui[b*MDIM + i];
        wr = g_Wr[b*MDIM + i]; wi = g_Wi[b*MDIM + i];
    }
    float ayr = g_AYr[b*MDIM + i], ayi = g_AYi[b*MDIM + i];
    float lam = g_Lam[b*MDIM + i];
    float Dm = g_D[i];
    float eps;
    if (k > 0) {
        // eps1 = ||Y||^2 - 2 Re<AY,U> + Re<U, AA U>
        float loc = ur*wr + ui*wi - 2.f*(ayr*ur + ayi*ui);
        #pragma unroll
        for (int o = 16; o > 0; o >>= 1) loc += __shfl_down_sync(0xffffffffu, loc, o);
        if (lane == 0) sr1[w] = loc;
        __syncthreads();
        if (i == 0) {
            float s = 0.f;
            #pragma unroll
            for (int q = 0; q < 8; q++) s += sr1[q];
            float eps1 = g_Yn[b] + s;
            float a = a0p[0] + (float)NMEAS;
            sEps = a / (b0p[0] + eps1 + g_eps2[b] + 1e-6f);
        }
        __syncthreads();
        eps = sEps;
    } else {
        eps = a0p[0] / b0p[0];
    }
    float sig = 1.f / (eps*Dm + lam + 1e-6f);
    float Tk = g_T[b*10 + k];
    float inv = eps / (eps*Tk + lam + 1e-6f);
    float unr = inv * (Tk*ur - wr + ayr);
    float uni = inv * (Tk*ui - wi + ayi);
    if (k < LNUM - 1) {
        // eps2 = sum D*Sigma (stored for next layer's eps)
        float v = Dm * sig;
        #pragma unroll
        for (int o = 16; o > 0; o >>= 1) v += __shfl_down_sync(0xffffffffu, v, o);
        __syncthreads();
        if (lane == 0) sr1[w] = v;
        __syncthreads();
        if (i == 0) {
            float s = 0.f;
            #pragma unroll
            for (int q = 0; q < 8; q++) s += sr1[q];
            g_eps2[b] = s;
        }
        g_Ur[b*MDIM + i] = unr;
        g_Ui[b*MDIM + i] = uni;
        float ck = g_c[b*9 + k], dk = g_d[b*9 + k];
        g_Lam[b*MDIM + i] = (ck + 1.f) / (dk + unr*unr + uni*uni + sig + 1e-6f);
    } else {
        float v = sqrtf(unr*unr + uni*uni);
        out[b*MDIM + i] = v;
        float mv = v;
        #pragma unroll
        for (int o = 16; o > 0; o >>= 1) mv = fmaxf(mv, __shfl_down_sync(0xffffffffu, mv, o));
        __syncthreads();
        if (lane == 0) sr1[w] = mv;
        __syncthreads();
        if (i == 0) {
            float s = sr1[0];
            #pragma unroll
            for (int q = 1; q < 8; q++) s = fmaxf(s, sr1[q]);
            atomicMax(&g_max, __float_as_uint(s));
        }
    }
}

// ---------------- K10: scale + diagnostic tails ----------------------------
__global__ void k_final(float* __restrict__ out) {
    int bid = blockIdx.x;
    if (bid < BATCH) {
        int idx = bid * 256 + threadIdx.x;
        float mx = __uint_as_float(g_max);
        out[idx] = out[idx] / (mx + 1e-8f);
    } else {
        int t = threadIdx.x;
        int base = BATCH * MDIM;
        if (t < 9)       out[base + t] = g_c[(BATCH - 1)*9 + t];
        else if (t < 18) out[base + t] = g_d[(BATCH - 1)*9 + (t - 9)];
        else if (t < 28) out[base + t] = g_T[(BATCH - 1)*10 + (t - 18)];
    }
}

// ---------------- launch ---------------------------------------------------
extern "C" void kernel_launch(void* const* d_in, const int* in_sizes, int n_in,
                              void* d_out, int out_size) {
    const float* Yr  = (const float*)d_in[0];
    const float* Yi  = (const float*)d_in[1];
    const float* Ar  = (const float*)d_in[2];
    const float* Ai  = (const float*)d_in[3];
    const float* c1w = (const float*)d_in[4];
    const float* c1b = (const float*)d_in[5];
    const float* c2w = (const float*)d_in[6];
    const float* c2b = (const float*)d_in[7];
    const float* hcw = (const float*)d_in[8];
    const float* hcb = (const float*)d_in[9];
    const float* hdw = (const float*)d_in[10];
    const float* hdb = (const float*)d_in[11];
    const float* hTw = (const float*)d_in[12];
    const float* hTb = (const float*)d_in[13];
    const float* a0  = (const float*)d_in[14];
    const float* b0  = (const float*)d_in[15];
    float* out = (float*)d_out;

    int conv2_smem = 12288*4 + 32*18*CPITCH*8;          // 49152 + 50688 = 99840
    int heads_smem = (64*130 + 28*192)*4;               // 54784
    cudaFuncSetAttribute(k_conv2, cudaFuncAttributeMaxDynamicSharedMemorySize, conv2_smem);
    cudaFuncSetAttribute(k_heads, cudaFuncAttributeMaxDynamicSharedMemorySize, heads_smem);

    k_prep<<<256, 256>>>(Ar, Ai);
    k_ay<<<256, 256>>>(Yr, Yi, Ar, Ai);
    k_conv1<<<dim3(64, 8), 256>>>(c1w, c1b);
    k_conv2<<<dim3(128, 2, 2), 128, conv2_smem>>>(c2w, c2b);
    k_heads<<<16, 128, heads_smem>>>(hcw, hcb, hdw, hdb, hTw, hTb);
    k_init<<<BATCH, 256>>>(Yr, Yi);

    for (int k = 0; k < LNUM; k++) {
        if (k > 0) k_mm<<<dim3(32, 4), 256>>>();
        k_up<<<BATCH, 256>>>(k, a0, b0, out);
    }
    k_final<<<2049, 256>>>(out);
}

// round 7
// speedup vs baseline: 1.8578x; 1.0171x over previous
#include <cuda_runtime.h>
#include <math.h>

#define BATCH 2048
#define NMEAS 128
#define MDIM  256
#define LNUM  10

typedef unsigned long long ull;

__device__ __forceinline__ ull pk2(float x, float y) {
    ull r; asm("mov.b64 %0, {%1, %2};" : "=l"(r) : "f"(x), "f"(y)); return r;
}
__device__ __forceinline__ float2 upk2(ull v) {
    float2 t; asm("mov.b64 {%0, %1}, %2;" : "=f"(t.x), "=f"(t.y) : "l"(v)); return t;
}
__device__ __forceinline__ void fma2(ull& d, ull a, ull b) {
    asm("fma.rn.f32x2 %0, %1, %2, %3;" : "=l"(d) : "l"(a), "l"(b), "l"(d));
}

// ---------------- scratch ----------------
__device__ float g_AAr[MDIM*MDIM], g_AAi[MDIM*MDIM];
__device__ float g_D[MDIM];
__device__ float g_AYr[BATCH*MDIM], g_AYi[BATCH*MDIM];
__device__ float g_AYtr[MDIM*BATCH], g_AYti[MDIM*BATCH];
__device__ float g_F1[32*MDIM*BATCH];
__device__ float g_fmp[2*64*BATCH];
__device__ float g_c[BATCH*9], g_d[BATCH*9], g_T[BATCH*10];
__device__ float g_Ur[BATCH*MDIM], g_Ui[BATCH*MDIM];
__device__ float g_Wr[BATCH*MDIM], g_Wi[BATCH*MDIM];
__device__ float g_Lam[BATCH*MDIM];
__device__ float g_eps2[BATCH], g_Yn[BATCH];
__device__ unsigned int g_max;

extern __shared__ float sm2[];

// ---------------- K0: AA = A^H A, D ----------
__global__ void k_prep(const float* __restrict__ Ar, const float* __restrict__ Ai) {
    int i = blockIdx.x, j = threadIdx.x;
    __shared__ float cr[NMEAS], ci[NMEAS];
    if (j < NMEAS) { cr[j] = Ar[j*MDIM + i]; ci[j] = Ai[j*MDIM + i]; }
    __syncthreads();
    float sr = 0.f, si = 0.f;
    for (int n = 0; n < NMEAS; n++) {
        float arj = Ar[n*MDIM + j], aij = Ai[n*MDIM + j];
        sr += cr[n]*arj + ci[n]*aij;
        si += cr[n]*aij - ci[n]*arj;
    }
    g_AAr[i*MDIM + j] = sr;
    g_AAi[i*MDIM + j] = si;
    if (j == i) g_D[i] = sr;
    if (i == 0 && j == 0) g_max = 0u;
}

// ---------------- K1: AY = A^H Y (+ transposed copy) ----------------------
__global__ void k_ay(const float* __restrict__ Yr, const float* __restrict__ Yi,
                     const float* __restrict__ Ar, const float* __restrict__ Ai) {
    int b0 = blockIdx.x * 8;
    __shared__ float sYr[8][NMEAS], sYi[8][NMEAS];
    for (int idx = threadIdx.x; idx < 8*NMEAS; idx += 256) {
        int bl = idx >> 7, n = idx & 127;
        sYr[bl][n] = Yr[(b0 + bl)*NMEAS + n];
        sYi[bl][n] = Yi[(b0 + bl)*NMEAS + n];
    }
    __syncthreads();
    int m = threadIdx.x;
    float ayr[8], ayi[8];
    #pragma unroll
    for (int q = 0; q < 8; q++) { ayr[q] = 0.f; ayi[q] = 0.f; }
    for (int n = 0; n < NMEAS; n++) {
        float ar = Ar[n*MDIM + m], ai = Ai[n*MDIM + m];
        #pragma unroll
        for (int q = 0; q < 8; q++) {
            float yr = sYr[q][n], yi = sYi[q][n];
            ayr[q] += ar*yr + ai*yi;
            ayi[q] += ar*yi - ai*yr;
        }
    }
    #pragma unroll
    for (int q = 0; q < 8; q++) {
        g_AYr[(b0 + q)*MDIM + m] = ayr[q];
        g_AYi[(b0 + q)*MDIM + m] = ayi[q];
        g_AYtr[m*BATCH + b0 + q] = ayr[q];
        g_AYti[m*BATCH + b0 + q] = ayi[q];
    }
}

// ---------------- K2: conv1 (2->32, 3x3) + relu, f32x2 h-pairs -------------
__global__ __launch_bounds__(256) void k_conv1(const float* __restrict__ w1,
                                               const float* __restrict__ b1) {
    __shared__ float ws[576];
    __shared__ float bs[32];
    __shared__ float2 px[2*34*11];
    int tid = threadIdx.x;
    int w0 = blockIdx.x * 32;
    int hbase = blockIdx.y * 32;
    for (int idx = tid; idx < 576; idx += 256) ws[idx] = w1[idx];
    if (tid < 32) bs[tid] = b1[tid];
    int wl = tid & 31, og = tid >> 5;
    int oc0 = og * 4;
    for (int hc = 0; hc < 2; hc++) {
        int hb = hbase + hc*16;
        __syncthreads();
        for (int idx = tid; idx < 680; idx += 256) {
            int ic = idx / 340, r = idx % 340, wll = r / 10, t = r % 10;
            int h1 = hb - 1 + t, h2 = h1 + 8;
            int w = w0 - 1 + wll;
            bool wok = (w >= 0 && w < BATCH);
            const float* src = ic ? g_AYti : g_AYtr;
            float v1 = (wok && h1 >= 0 && h1 < MDIM) ? src[h1*BATCH + w] : 0.f;
            float v2 = (wok && h2 < MDIM)            ? src[h2*BATCH + w] : 0.f;
            px[(ic*34 + wll)*11 + t] = make_float2(v1, v2);
        }
        __syncthreads();
        ull acc[4][8];
        #pragma unroll
        for (int o = 0; o < 4; o++) {
            ull bp = pk2(bs[oc0 + o], bs[oc0 + o]);
            #pragma unroll
            for (int p = 0; p < 8; p++) acc[o][p] = bp;
        }
        #pragma unroll
        for (int ic = 0; ic < 2; ic++) {
            #pragma unroll
            for (int kw = 0; kw < 3; kw++) {
                const float2* pp = px + (ic*34 + wl + kw)*11;
                ull xp[10];
                #pragma unroll
                for (int t = 0; t < 10; t++) xp[t] = *(const ull*)(pp + t);
                #pragma unroll
                for (int kh = 0; kh < 3; kh++) {
                    ull wp[4];
                    #pragma unroll
                    for (int o = 0; o < 4; o++) {
                        float wv = ws[(oc0 + o)*18 + ic*9 + kh*3 + kw];
                        wp[o] = pk2(wv, wv);
                    }
                    #pragma unroll
                    for (int p = 0; p < 8; p++) {
                        fma2(acc[0][p], wp[0], xp[p + kh]);
                        fma2(acc[1][p], wp[1], xp[p + kh]);
                        fma2(acc[2][p], wp[2], xp[p + kh]);
                        fma2(acc[3][p], wp[3], xp[p + kh]);
                    }
                }
            }
        }
        #pragma unroll
        for (int o = 0; o < 4; o++) {
            int oc = oc0 + o;
            #pragma unroll
            for (int p = 0; p < 8; p++) {
                float2 v = upk2(acc[o][p]);
                g_F1[(oc*MDIM + hb + p)*BATCH + w0 + wl]     = fmaxf(v.x, 0.f);
                g_F1[(oc*MDIM + hb + 8 + p)*BATCH + w0 + wl] = fmaxf(v.y, 0.f);
            }
        }
    }
}

// ---------------- K3: conv2 (R4 version, verbatim): 256 thr, 2 oc/thread ---
#define CPITCH 11
__global__ __launch_bounds__(256) void k_conv2(const float* __restrict__ w2,
                                               const float* __restrict__ b2) {
    float* wsm = sm2;                          // 9216 floats (32 oc)
    float2* px = (float2*)(sm2 + 9216);        // 32*18*11 float2
    __shared__ float bs[32];
    int tid = threadIdx.x;
    int w0 = blockIdx.x * 16;
    int by = blockIdx.y;
    int oz = blockIdx.z;
    for (int idx = tid; idx < 9216; idx += 256) wsm[idx] = w2[oz*9216 + idx];
    if (tid < 32) bs[tid] = b2[oz*32 + tid];
    int wl = tid & 15, og = tid >> 4;
    int o0 = og, o1 = og + 16;
    float sum2[2] = {0.f, 0.f};
    for (int hc = 0; hc < 8; hc++) {
        int hb = by*128 + hc*16;
        __syncthreads();
        for (int idx = tid; idx < 5760; idx += 256) {
            int ic = idx / 180, r = idx % 180, t = r / 18, wll = r % 18;
            int h1 = hb - 1 + t, h2 = h1 + 8;
            int w = w0 - 1 + wll;
            bool wok = (w >= 0 && w < BATCH);
            const float* base = g_F1 + (size_t)ic*MDIM*BATCH + w;
            float v1 = (wok && h1 >= 0 && h1 < MDIM) ? base[(size_t)h1*BATCH] : 0.f;
            float v2 = (wok && h2 < MDIM)            ? base[(size_t)h2*BATCH] : 0.f;
            px[(ic*18 + wll)*CPITCH + t] = make_float2(v1, v2);
        }
        __syncthreads();
        ull acc[2][8];
        {
            ull b0p = pk2(bs[o0], bs[o0]);
            ull b1p = pk2(bs[o1], bs[o1]);
            #pragma unroll
            for (int p = 0; p < 8; p++) { acc[0][p] = b0p; acc[1][p] = b1p; }
        }
        for (int ic = 0; ic < 32; ic++) {
            const float2* pb = px + (ic*18 + wl)*CPITCH;
            const float* wb = wsm + ic*9;
            #pragma unroll
            for (int kw = 0; kw < 3; kw++) {
                const float2* pp = pb + kw*CPITCH;
                ull xp[10];
                #pragma unroll
                for (int t = 0; t < 10; t++) xp[t] = *(const ull*)(pp + t);
                #pragma unroll
                for (int kh = 0; kh < 3; kh++) {
                    float wv0 = wb[o0*288 + kh*3 + kw];
                    float wv1 = wb[o1*288 + kh*3 + kw];
                    ull wp0 = pk2(wv0, wv0);
                    ull wp1 = pk2(wv1, wv1);
                    #pragma unroll
                    for (int p = 0; p < 8; p++) {
                        fma2(acc[0][p], wp0, xp[p + kh]);
                        fma2(acc[1][p], wp1, xp[p + kh]);
                    }
                }
            }
        }
        #pragma unroll
        for (int o = 0; o < 2; o++)
            #pragma unroll
            for (int p = 0; p < 8; p++) {
                float2 v = upk2(acc[o][p]);
                sum2[o] += fmaxf(v.x, 0.f) + fmaxf(v.y, 0.f);
            }
    }
    g_fmp[(by*64 + oz*32 + o0)*BATCH + w0 + wl] = sum2[0] * (1.f / 256.f);
    g_fmp[(by*64 + oz*32 + o1)*BATCH + w0 + wl] = sum2[1] * (1.f / 256.f);
}

// ---------------- K4: conv1d heads --------------------------------
__global__ __launch_bounds__(128) void k_heads(
        const float* __restrict__ hcw, const float* __restrict__ hcb,
        const float* __restrict__ hdw, const float* __restrict__ hdb,
        const float* __restrict__ hTw, const float* __restrict__ hTb) {
    float* sf = sm2;              // 64 * 130
    float* sw = sm2 + 64*130;     // 28 * 192
    __shared__ float sb[28];
    int tid = threadIdx.x;
    int b0 = blockIdx.x * 128;
    for (int idx = tid; idx < 64*130; idx += 128) {
        int ic = idx / 130, off = idx % 130;
        int b = b0 - 1 + off;
        float v = 0.f;
        if (b >= 0 && b < BATCH) v = g_fmp[ic*BATCH + b] + g_fmp[(64 + ic)*BATCH + b];
        sf[idx] = v;
    }
    for (int idx = tid; idx < 28*192; idx += 128) {
        int l = idx / 192, r = idx % 192;
        sw[idx] = (l < 9) ? hcw[l*192 + r] : (l < 18) ? hdw[(l-9)*192 + r] : hTw[(l-18)*192 + r];
    }
    if (tid < 28) sb[tid] = (tid < 9) ? hcb[tid] : (tid < 18) ? hdb[tid-9] : hTb[tid-18];
    __syncthreads();
    float acc[28];
    #pragma unroll
    for (int l = 0; l < 28; l++) acc[l] = sb[l];
    for (int ic = 0; ic < 64; ic++) {
        float x0 = sf[ic*130 + tid];
        float x1 = sf[ic*130 + tid + 1];
        float x2 = sf[ic*130 + tid + 2];
        #pragma unroll
        for (int l = 0; l < 28; l++) {
            const float* w = sw + l*192 + ic*3;
            acc[l] += w[0]*x0 + w[1]*x1 + w[2]*x2;
        }
    }
    int b = b0 + tid;
    #pragma unroll
    for (int l = 0; l < 28; l++) {
        float v = fabsf(acc[l]);
        if (l < 9)       { v = fminf(fmaxf(v, 1e-6f), 100.f); g_c[b*9 + l] = v; }
        else if (l < 18) { v = fmaxf(v, 1e-6f);               g_d[b*9 + (l-9)] = v; }
        else             { v = fminf(fmaxf(v, 1e-6f), 100.f); g_T[b*10 + (l-18)] = v; }
    }
}

// ---------------- K5: init: Lam, ||Y||^2 ----------------------------------
__global__ void k_init(const float* __restrict__ Yr, const float* __restrict__ Yi) {
    int b = blockIdx.x, i = threadIdx.x;
    __shared__ float sred[8];
    float lam = g_c[b*9] / g_d[b*9];
    g_Lam[b*MDIM + i] = lam;
    float v = 0.f;
    if (i < NMEAS) {
        float yr = Yr[b*NMEAS + i], yi = Yi[b*NMEAS + i];
        v = yr*yr + yi*yi;
    }
    int lane = i & 31, w = i >> 5;
    #pragma unroll
    for (int o = 16; o > 0; o >>= 1) v += __shfl_down_sync(0xffffffffu, v, o);
    if (lane == 0) sred[w] = v;
    __syncthreads();
    if (i == 0) {
        float s = 0.f;
        #pragma unroll
        for (int w2 = 0; w2 < 8; w2++) s += sred[w2];
        g_Yn[b] = s;
    }
}

// ---------------- K6: W = AA @ U. 64b x 32i tiles, 128 thr, grid (32,8) ----
// per-output k-accumulation order identical to R5 version (bitwise same W)
#define GP 17
__global__ __launch_bounds__(128) void k_mm() {
    __shared__ ull sU2[64*GP], sUs[64*GP], sA2[32*GP];
    int tid = threadIdx.x;
    int b0 = blockIdx.x * 64, i0 = blockIdx.y * 32;
    int tx = tid & 7, ty = tid >> 3;         // tx: i-group (0..7), ty: b-group (0..15)
    int lrU = tid >> 1, lcU = (tid & 1) * 8; // U fill: 64 rows x 16 cols
    int lrA = tid >> 2, lcA = (tid & 3) * 4; // A fill: 32 rows x 16 cols
    float4 fUr0 = *(const float4*)&g_Ur[(b0 + lrU)*MDIM + lcU];
    float4 fUr1 = *(const float4*)&g_Ur[(b0 + lrU)*MDIM + lcU + 4];
    float4 fUi0 = *(const float4*)&g_Ui[(b0 + lrU)*MDIM + lcU];
    float4 fUi1 = *(const float4*)&g_Ui[(b0 + lrU)*MDIM + lcU + 4];
    float4 fAr  = *(const float4*)&g_AAr[(i0 + lrA)*MDIM + lcA];
    float4 fAi  = *(const float4*)&g_AAi[(i0 + lrA)*MDIM + lcA];
    ull acc[4][4];
    #pragma unroll
    for (int u = 0; u < 4; u++)
        #pragma unroll
        for (int v = 0; v < 4; v++) acc[u][v] = 0ull;
    for (int jc = 0; jc < MDIM; jc += 16) {
        __syncthreads();
        {
            float ur[8] = {fUr0.x, fUr0.y, fUr0.z, fUr0.w, fUr1.x, fUr1.y, fUr1.z, fUr1.w};
            float ui[8] = {fUi0.x, fUi0.y, fUi0.z, fUi0.w, fUi1.x, fUi1.y, fUi1.z, fUi1.w};
            float ar[4] = {fAr.x, fAr.y, fAr.z, fAr.w};
            float ai[4] = {fAi.x, fAi.y, fAi.z, fAi.w};
            #pragma unroll
            for (int t = 0; t < 8; t++) {
                sU2[lrU*GP + lcU + t] = pk2(ur[t], ui[t]);
                sUs[lrU*GP + lcU + t] = pk2(-ui[t], ur[t]);
            }
            #pragma unroll
            for (int t = 0; t < 4; t++)
                sA2[lrA*GP + lcA + t] = pk2(ar[t], ai[t]);
        }
        __syncthreads();
        if (jc + 16 < MDIM) {
            int cU = jc + 16 + lcU, cA = jc + 16 + lcA;
            fUr0 = *(const float4*)&g_Ur[(b0 + lrU)*MDIM + cU];
            fUr1 = *(const float4*)&g_Ur[(b0 + lrU)*MDIM + cU + 4];
            fUi0 = *(const float4*)&g_Ui[(b0 + lrU)*MDIM + cU];
            fUi1 = *(const float4*)&g_Ui[(b0 + lrU)*MDIM + cU + 4];
            fAr  = *(const float4*)&g_AAr[(i0 + lrA)*MDIM + cA];
            fAi  = *(const float4*)&g_AAi[(i0 + lrA)*MDIM + cA];
        }
        #pragma unroll 4
        for (int j = 0; j < 16; j++) {
            ull u2[4], us[4];
            #pragma unroll
            for (int u = 0; u < 4; u++) {
                u2[u] = sU2[(ty + 16*u)*GP + j];
                us[u] = sUs[(ty + 16*u)*GP + j];
            }
            #pragma unroll
            for (int v = 0; v < 4; v++) {
                float2 a = upk2(sA2[(tx + 8*v)*GP + j]);
                ull arr = pk2(a.x, a.x);
                ull aii = pk2(a.y, a.y);
                #pragma unroll
                for (int u = 0; u < 4; u++) {
                    fma2(acc[u][v], arr, u2[u]);
                    fma2(acc[u][v], aii, us[u]);
                }
            }
        }
    }
    #pragma unroll
    for (int u = 0; u < 4; u++) {
        int b = b0 + ty + 16*u;
        #pragma unroll
        for (int v = 0; v < 4; v++) {
            int i = i0 + tx + 8*v;
            float2 cc = upk2(acc[u][v]);
            g_Wr[b*MDIM + i] = cc.x;
            g_Wi[b*MDIM + i] = cc.y;
        }
    }
}

// ---------------- K7: fused update: eps, Sigma, eps2, U (in place), Lam ----
__global__ __launch_bounds__(256) void k_up(int k,
        const float* __restrict__ a0p, const float* __restrict__ b0p,
        float* __restrict__ out) {
    int b = blockIdx.x, i = threadIdx.x;
    __shared__ float sr1[8];
    __shared__ float sEps;
    int lane = i & 31, w = i >> 5;
    float ur = 0.f, ui = 0.f, wr = 0.f, wi = 0.f;
    if (k > 0) {
        ur = g_Ur[b*MDIM + i]; ui = g_Ui[b*MDIM + i];
        wr = g_Wr[b*MDIM + i];
        wi = g_Wi[b*MDIM + i];
    }
    float ayr = g_AYr[b*MDIM + i], ayi = g_AYi[b*MDIM + i];
    float lam = g_Lam[b*MDIM + i];
    float Dm = g_D[i];
    float eps;
    if (k > 0) {
        float loc = ur*wr + ui*wi - 2.f*(ayr*ur + ayi*ui);
        #pragma unroll
        for (int o = 16; o > 0; o >>= 1) loc += __shfl_down_sync(0xffffffffu, loc, o);
        if (lane == 0) sr1[w] = loc;
        __syncthreads();
        if (i == 0) {
            float s = 0.f;
            #pragma unroll
            for (int q = 0; q < 8; q++) s += sr1[q];
            float eps1 = g_Yn[b] + s;
            float a = a0p[0] + (float)NMEAS;
            sEps = a / (b0p[0] + eps1 + g_eps2[b] + 1e-6f);
        }
        __syncthreads();
        eps = sEps;
    } else {
        eps = a0p[0] / b0p[0];
    }
    float sig = 1.f / (eps*Dm + lam + 1e-6f);
    float Tk = g_T[b*10 + k];
    float inv = eps / (eps*Tk + lam + 1e-6f);
    float unr = inv * (Tk*ur - wr + ayr);
    float uni = inv * (Tk*ui - wi + ayi);
    if (k < LNUM - 1) {
        float v = Dm * sig;
        #pragma unroll
        for (int o = 16; o > 0; o >>= 1) v += __shfl_down_sync(0xffffffffu, v, o);
        __syncthreads();
        if (lane == 0) sr1[w] = v;
        __syncthreads();
        if (i == 0) {
            float s = 0.f;
            #pragma unroll
            for (int q = 0; q < 8; q++) s += sr1[q];
            g_eps2[b] = s;
        }
        g_Ur[b*MDIM + i] = unr;
        g_Ui[b*MDIM + i] = uni;
        float ck = g_c[b*9 + k], dk = g_d[b*9 + k];
        g_Lam[b*MDIM + i] = (ck + 1.f) / (dk + unr*unr + uni*uni + sig + 1e-6f);
    } else {
        float v = sqrtf(unr*unr + uni*uni);
        out[b*MDIM + i] = v;
        float mv = v;
        #pragma unroll
        for (int o = 16; o > 0; o >>= 1) mv = fmaxf(mv, __shfl_down_sync(0xffffffffu, mv, o));
        __syncthreads();
        if (lane == 0) sr1[w] = mv;
        __syncthreads();
        if (i == 0) {
            float s = sr1[0];
            #pragma unroll
            for (int q = 1; q < 8; q++) s = fmaxf(s, sr1[q]);
            atomicMax(&g_max, __float_as_uint(s));
        }
    }
}

// ---------------- K10: scale + diagnostic tails ----------------------------
__global__ void k_final(float* __restrict__ out) {
    int bid = blockIdx.x;
    if (bid < BATCH) {
        int idx = bid * 256 + threadIdx.x;
        float mx = __uint_as_float(g_max);
        out[idx] = out[idx] / (mx + 1e-8f);
    } else {
        int t = threadIdx.x;
        int base = BATCH * MDIM;
        if (t < 9)       out[base + t] = g_c[(BATCH - 1)*9 + t];
        else if (t < 18) out[base + t] = g_d[(BATCH - 1)*9 + (t - 9)];
        else if (t < 28) out[base + t] = g_T[(BATCH - 1)*10 + (t - 18)];
    }
}

// ---------------- launch ---------------------------------------------------
extern "C" void kernel_launch(void* const* d_in, const int* in_sizes, int n_in,
                              void* d_out, int out_size) {
    const float* Yr  = (const float*)d_in[0];
    const float* Yi  = (const float*)d_in[1];
    const float* Ar  = (const float*)d_in[2];
    const float* Ai  = (const float*)d_in[3];
    const float* c1w = (const float*)d_in[4];
    const float* c1b = (const float*)d_in[5];
    const float* c2w = (const float*)d_in[6];
    const float* c2b = (const float*)d_in[7];
    const float* hcw = (const float*)d_in[8];
    const float* hcb = (const float*)d_in[9];
    const float* hdw = (const float*)d_in[10];
    const float* hdb = (const float*)d_in[11];
    const float* hTw = (const float*)d_in[12];
    const float* hTb = (const float*)d_in[13];
    const float* a0  = (const float*)d_in[14];
    const float* b0  = (const float*)d_in[15];
    float* out = (float*)d_out;

    int conv2_smem = 9216*4 + 32*18*CPITCH*8;           // 36864 + 50688 = 87552
    int heads_smem = (64*130 + 28*192)*4;               // 54784
    cudaFuncSetAttribute(k_conv2, cudaFuncAttributeMaxDynamicSharedMemorySize, conv2_smem);
    cudaFuncSetAttribute(k_heads, cudaFuncAttributeMaxDynamicSharedMemorySize, heads_smem);

    k_prep<<<256, 256>>>(Ar, Ai);
    k_ay<<<256, 256>>>(Yr, Yi, Ar, Ai);
    k_conv1<<<dim3(64, 8), 256>>>(c1w, c1b);
    k_conv2<<<dim3(128, 2, 2), 256, conv2_smem>>>(c2w, c2b);
    k_heads<<<16, 128, heads_smem>>>(hcw, hcb, hdw, hdb, hTw, hTb);
    k_init<<<BATCH, 256>>>(Yr, Yi);

    for (int k = 0; k < LNUM; k++) {
        if (k > 0) k_mm<<<dim3(32, 8), 128>>>();
        k_up<<<BATCH, 256>>>(k, a0, b0, out);
    }
    k_final<<<2049, 256>>>(out);
}